// round 7
// baseline (speedup 1.0000x reference)
#include <cuda_runtime.h>
#include <math.h>
#include <stdint.h>

// Problem constants
#define NN   100000
#define FIN  64
#define CC   128
#define HH   2
#define DD   64
#define EE   600000
#define MT   2
#define OUTD 8
#define KPAD 4

// ---------------------------------------------------------------------------
// Scratch (device globals — no allocation allowed)
// ---------------------------------------------------------------------------
__device__ float    g_h[(size_t)NN * CC];
__device__ float    g_out0[(size_t)NN * CC];
__device__ float    g_out1[(size_t)NN * CC];
__device__ float    g_asrc[MT * NN * HH];
__device__ float    g_adst[MT * NN * HH];
__device__ float    g_alpha[(size_t)EE * HH];
__device__ float    g_asum[NN * HH];
__device__ float    g_colsum[MT * CC];
__device__ float    g_attn[MT];

// ---------------------------------------------------------------------------
// Helpers
// ---------------------------------------------------------------------------
__device__ __forceinline__ float tanh_fast(float x) {
    float y;
    asm("tanh.approx.f32 %0, %1;" : "=f"(y) : "f"(x));
    return y;
}
__device__ __forceinline__ void red_add_v4(float* p, float x, float y, float z, float w) {
    asm volatile("red.global.add.v4.f32 [%0], {%1,%2,%3,%4};"
                 :: "l"(p), "f"(x), "f"(y), "f"(z), "f"(w) : "memory");
}
__device__ __forceinline__ void red_add_v2(float* p, float x, float y) {
    asm volatile("red.global.add.v2.f32 [%0], {%1,%2};"
                 :: "l"(p), "f"(x), "f"(y) : "memory");
}
__device__ __forceinline__ uint32_t f2tf32(float f) {
    uint32_t u;
    asm("cvt.rna.tf32.f32 %0, %1;" : "=r"(u) : "f"(f));
    return u;
}
__device__ __forceinline__ void mma_tf32(float& c0, float& c1, float& c2, float& c3,
                                         uint32_t a0, uint32_t a1, uint32_t a2, uint32_t a3,
                                         uint32_t b0, uint32_t b1) {
    asm volatile(
        "mma.sync.aligned.m16n8k8.row.col.f32.tf32.tf32.f32 "
        "{%0,%1,%2,%3}, {%4,%5,%6,%7}, {%8,%9}, {%0,%1,%2,%3};"
        : "+f"(c0), "+f"(c1), "+f"(c2), "+f"(c3)
        : "r"(a0), "r"(a1), "r"(a2), "r"(a3), "r"(b0), "r"(b1));
}

// ---------------------------------------------------------------------------
// tf32 tensor-core GEMM: out[n,c] = A[n,:K] @ W[K,128] + b[c]
// Block: 128-row x 128-col tile, 256 threads (8 warps x 16 rows each).
// FUSED: A row := attn0*relu(A)+attn1*relu(A2)  (layer-2 combine fusion)
// ---------------------------------------------------------------------------
template <int K, bool FUSED>
__global__ void __launch_bounds__(256)
gemm_tf32_kernel(const float* __restrict__ A,
                 const float* __restrict__ A2,
                 const float* __restrict__ attn,
                 const float* __restrict__ W,
                 const float* __restrict__ b,
                 float* __restrict__ out) {
    extern __shared__ uint32_t smem[];
    uint32_t* sW = smem;             // [K][128] tf32
    uint32_t* sA = smem + K * 128;   // [128][K+KPAD] tf32
    const int tid = threadIdx.x;
    const int warp = tid >> 5;
    const int lane = tid & 31;
    const int gid4 = lane >> 2;      // 0..7
    const int tig = lane & 3;        // 0..3
    const int row0 = blockIdx.x * 128;

    // Stage W as tf32
    for (int idx = tid; idx < K * 32; idx += 256) {
        float4 w4 = ((const float4*)W)[idx];
        uint4 u = make_uint4(f2tf32(w4.x), f2tf32(w4.y), f2tf32(w4.z), f2tf32(w4.w));
        ((uint4*)sW)[idx] = u;
    }
    // Stage A tile as tf32 (optionally fused combine+relu)
    float a0f = 0.f, a1f = 0.f;
    if (FUSED) { a0f = attn[0]; a1f = attn[1]; }
    for (int idx = tid; idx < 128 * (K / 4); idx += 256) {
        int r = idx / (K / 4), k4 = idx % (K / 4);
        float4 v = make_float4(0.f, 0.f, 0.f, 0.f);
        if (row0 + r < NN) {
            if (FUSED) {
                float4 u = ((const float4*)(A + (size_t)(row0 + r) * K))[k4];
                float4 w = ((const float4*)(A2 + (size_t)(row0 + r) * K))[k4];
                v.x = a0f * fmaxf(u.x, 0.f) + a1f * fmaxf(w.x, 0.f);
                v.y = a0f * fmaxf(u.y, 0.f) + a1f * fmaxf(w.y, 0.f);
                v.z = a0f * fmaxf(u.z, 0.f) + a1f * fmaxf(w.z, 0.f);
                v.w = a0f * fmaxf(u.w, 0.f) + a1f * fmaxf(w.w, 0.f);
            } else {
                v = ((const float4*)(A + (size_t)(row0 + r) * K))[k4];
            }
        }
        uint4 u4 = make_uint4(f2tf32(v.x), f2tf32(v.y), f2tf32(v.z), f2tf32(v.w));
        *(uint4*)&sA[r * (K + KPAD) + k4 * 4] = u4;
    }
    __syncthreads();

    const int wr = warp * 16;
    float c[16][4];
#pragma unroll
    for (int nt = 0; nt < 16; ++nt)
#pragma unroll
        for (int j = 0; j < 4; ++j) c[nt][j] = 0.0f;

#pragma unroll
    for (int ks = 0; ks < K / 8; ++ks) {
        const int k0 = ks * 8;
        uint32_t fa0 = sA[(wr + gid4) * (K + KPAD) + k0 + tig];
        uint32_t fa1 = sA[(wr + 8 + gid4) * (K + KPAD) + k0 + tig];
        uint32_t fa2 = sA[(wr + gid4) * (K + KPAD) + k0 + 4 + tig];
        uint32_t fa3 = sA[(wr + 8 + gid4) * (K + KPAD) + k0 + 4 + tig];
#pragma unroll
        for (int nt = 0; nt < 16; ++nt) {
            uint32_t fb0 = sW[(k0 + tig) * 128 + nt * 8 + gid4];
            uint32_t fb1 = sW[(k0 + 4 + tig) * 128 + nt * 8 + gid4];
            mma_tf32(c[nt][0], c[nt][1], c[nt][2], c[nt][3],
                     fa0, fa1, fa2, fa3, fb0, fb1);
        }
    }

    const int rowa = row0 + wr + gid4;
    const int rowb = rowa + 8;
#pragma unroll
    for (int nt = 0; nt < 16; ++nt) {
        int col = nt * 8 + 2 * tig;
        float2 bb = *(const float2*)&b[col];
        if (rowa < NN)
            *(float2*)&out[(size_t)rowa * 128 + col] =
                make_float2(c[nt][0] + bb.x, c[nt][1] + bb.y);
        if (rowb < NN)
            *(float2*)&out[(size_t)rowb * 128 + col] =
                make_float2(c[nt][2] + bb.x, c[nt][3] + bb.y);
    }
}

// ---------------------------------------------------------------------------
// tf32 semantic GEMM: colsum[c] += sum_n tanh( relu(A[n,:]) @ kw[:,c] + kb[c] )
// ---------------------------------------------------------------------------
__global__ void __launch_bounds__(256)
semantic_tf32_kernel(const float* __restrict__ A,
                     const float* __restrict__ kw,
                     const float* __restrict__ kb,
                     float* __restrict__ colsum) {
    extern __shared__ uint32_t smem[];
    uint32_t* sW = smem;               // [128][128]
    uint32_t* sA = smem + 128 * 128;   // [128][128+KPAD]
    __shared__ float scol[128];
    const int tid = threadIdx.x;
    const int warp = tid >> 5;
    const int lane = tid & 31;
    const int gid4 = lane >> 2;
    const int tig = lane & 3;
    const int row0 = blockIdx.x * 128;

    for (int idx = tid; idx < 128 * 32; idx += 256) {
        float4 w4 = ((const float4*)kw)[idx];
        uint4 u = make_uint4(f2tf32(w4.x), f2tf32(w4.y), f2tf32(w4.z), f2tf32(w4.w));
        ((uint4*)sW)[idx] = u;
    }
    if (tid < 128) scol[tid] = 0.0f;
    for (int idx = tid; idx < 128 * 32; idx += 256) {
        int r = idx >> 5, k4 = idx & 31;
        float4 v = make_float4(0.f, 0.f, 0.f, 0.f);
        if (row0 + r < NN) {
            float4 u = ((const float4*)(A + (size_t)(row0 + r) * 128))[k4];
            v = make_float4(fmaxf(u.x, 0.f), fmaxf(u.y, 0.f),
                            fmaxf(u.z, 0.f), fmaxf(u.w, 0.f));
        }
        uint4 u4 = make_uint4(f2tf32(v.x), f2tf32(v.y), f2tf32(v.z), f2tf32(v.w));
        *(uint4*)&sA[r * (128 + KPAD) + k4 * 4] = u4;
    }
    __syncthreads();

    const int wr = warp * 16;
    float c[16][4];
#pragma unroll
    for (int nt = 0; nt < 16; ++nt)
#pragma unroll
        for (int j = 0; j < 4; ++j) c[nt][j] = 0.0f;

#pragma unroll
    for (int ks = 0; ks < 16; ++ks) {
        const int k0 = ks * 8;
        uint32_t fa0 = sA[(wr + gid4) * (128 + KPAD) + k0 + tig];
        uint32_t fa1 = sA[(wr + 8 + gid4) * (128 + KPAD) + k0 + tig];
        uint32_t fa2 = sA[(wr + gid4) * (128 + KPAD) + k0 + 4 + tig];
        uint32_t fa3 = sA[(wr + 8 + gid4) * (128 + KPAD) + k0 + 4 + tig];
#pragma unroll
        for (int nt = 0; nt < 16; ++nt) {
            uint32_t fb0 = sW[(k0 + tig) * 128 + nt * 8 + gid4];
            uint32_t fb1 = sW[(k0 + 4 + tig) * 128 + nt * 8 + gid4];
            mma_tf32(c[nt][0], c[nt][1], c[nt][2], c[nt][3],
                     fa0, fa1, fa2, fa3, fb0, fb1);
        }
    }

    const int rowa = row0 + wr + gid4;
    const int rowb = rowa + 8;
#pragma unroll
    for (int nt = 0; nt < 16; ++nt) {
        int col = nt * 8 + 2 * tig;
        float2 bb = *(const float2*)&kb[col];
        float s0 = 0.f, s1 = 0.f;
        if (rowa < NN) {
            s0 += tanh_fast(c[nt][0] + bb.x);
            s1 += tanh_fast(c[nt][1] + bb.y);
        }
        if (rowb < NN) {
            s0 += tanh_fast(c[nt][2] + bb.x);
            s1 += tanh_fast(c[nt][3] + bb.y);
        }
        atomicAdd(&scol[col], s0);
        atomicAdd(&scol[col + 1], s1);
    }
    __syncthreads();
    if (tid < 128) atomicAdd(&colsum[tid], scol[tid]);
}

// ---------------------------------------------------------------------------
// Per-node attention logits, warp per node
// ---------------------------------------------------------------------------
__global__ void node_attn_kernel(const float* __restrict__ h,
                                 const float* __restrict__ att_src,
                                 const float* __restrict__ att_dst,
                                 float* __restrict__ asrc,
                                 float* __restrict__ adst, int n) {
    int gid = blockIdx.x * blockDim.x + threadIdx.x;
    int node = gid >> 5;
    int lane = gid & 31;
    if (node >= n) return;
    const float* hrow = h + (size_t)node * CC;
    float h00 = hrow[lane];
    float h01 = hrow[lane + 32];
    float h10 = hrow[lane + 64];
    float h11 = hrow[lane + 96];

    float r[8];
#pragma unroll
    for (int t = 0; t < MT; ++t) {
        const float* as = att_src + t * CC;
        const float* ad = att_dst + t * CC;
        r[t * 4 + 0] = h00 * as[lane] + h01 * as[lane + 32];
        r[t * 4 + 1] = h10 * as[lane + 64] + h11 * as[lane + 96];
        r[t * 4 + 2] = h00 * ad[lane] + h01 * ad[lane + 32];
        r[t * 4 + 3] = h10 * ad[lane + 64] + h11 * ad[lane + 96];
    }
#pragma unroll
    for (int i = 0; i < 8; ++i) {
#pragma unroll
        for (int off = 16; off > 0; off >>= 1)
            r[i] += __shfl_xor_sync(0xffffffffu, r[i], off);
    }
    if (lane == 0) {
#pragma unroll
        for (int t = 0; t < MT; ++t) {
            asrc[t * (NN * HH) + node * HH + 0] = r[t * 4 + 0];
            asrc[t * (NN * HH) + node * HH + 1] = r[t * 4 + 1];
            adst[t * (NN * HH) + node * HH + 0] = r[t * 4 + 2];
            adst[t * (NN * HH) + node * HH + 1] = r[t * 4 + 3];
        }
    }
}

// ---------------------------------------------------------------------------
// Edge softmax: alpha = exp(leaky(asrc[src]+adst[dst])); asum[dst] += alpha
// (shift-invariant softmax, bounded logits — validated in R3/R4)
// ---------------------------------------------------------------------------
__global__ void edge_softmax_kernel(const int* __restrict__ ei,
                                    const float* __restrict__ asrc,
                                    const float* __restrict__ adst,
                                    float* __restrict__ alpha,
                                    float* __restrict__ asum) {
    int e = blockIdx.x * blockDim.x + threadIdx.x;
    if (e >= EE) return;
    int src = ei[e];
    int dst = ei[EE + e];
    float2 s = *(const float2*)&asrc[src * HH];
    float2 d = *(const float2*)&adst[dst * HH];
    float a0 = s.x + d.x;
    float a1 = s.y + d.y;
    float l0 = (a0 > 0.0f) ? a0 : 0.2f * a0;
    float l1 = (a1 > 0.0f) ? a1 : 0.2f * a1;
    float ex0 = expf(l0);
    float ex1 = expf(l1);
    *(float2*)&alpha[(size_t)e * HH] = make_float2(ex0, ex1);
    red_add_v2(&asum[dst * HH], ex0, ex1);
}

// ---------------------------------------------------------------------------
// Edge message: out[dst] += h[src] * coef   (32 lanes/edge, v4 red)
// ---------------------------------------------------------------------------
__global__ void edge_message_kernel(const int* __restrict__ ei,
                                    const float* __restrict__ expalpha,
                                    const float* __restrict__ asum,
                                    const float* __restrict__ h,
                                    float* __restrict__ outT) {
    int gid = blockIdx.x * blockDim.x + threadIdx.x;
    int e = gid >> 5;
    int lane = gid & 31;
    if (e >= EE) return;
    int src = ei[e];
    int dst = ei[EE + e];
    int head = lane >> 4;
    float coef = expalpha[(size_t)e * HH + head] /
                 (asum[dst * HH + head] + 1e-16f);
    const float4* hrow = reinterpret_cast<const float4*>(h + (size_t)src * CC);
    float4 v = hrow[lane];
    float* o = outT + (size_t)dst * CC + lane * 4;
    red_add_v4(o, v.x * coef, v.y * coef, v.z * coef, v.w * coef);
}

// ---------------------------------------------------------------------------
// Semantic score + softmax (single block, 128 threads)
// ---------------------------------------------------------------------------
__global__ void score_softmax_kernel(const float* __restrict__ q,
                                     const float* __restrict__ colsum,
                                     float* __restrict__ attn) {
    __shared__ float red[128];
    int c = threadIdx.x;
    float s[MT];
#pragma unroll
    for (int m = 0; m < MT; ++m) {
        red[c] = q[c] * colsum[m * CC + c];
        __syncthreads();
        for (int off = 64; off > 0; off >>= 1) {
            if (c < off) red[c] += red[c + off];
            __syncthreads();
        }
        s[m] = red[0] * (1.0f / (float)NN);
        __syncthreads();
    }
    if (c == 0) {
        float mx = fmaxf(s[0], s[1]);
        float e0 = expf(s[0] - mx), e1 = expf(s[1] - mx);
        float inv = 1.0f / (e0 + e1);
        attn[0] = e0 * inv;
        attn[1] = e1 * inv;
    }
}

// ---------------------------------------------------------------------------
// Final linear fused with combine: warp per node
// ---------------------------------------------------------------------------
__global__ void final_linear_kernel(const float* __restrict__ o0,
                                    const float* __restrict__ o1,
                                    const float* __restrict__ attn,
                                    const float* __restrict__ lw,
                                    const float* __restrict__ lb,
                                    float* __restrict__ out) {
    int gid = blockIdx.x * blockDim.x + threadIdx.x;
    int node = gid >> 5;
    int lane = gid & 31;
    if (node >= NN) return;
    float a0 = attn[0], a1 = attn[1];
    float4 u = ((const float4*)(o0 + (size_t)node * CC))[lane];
    float4 v = ((const float4*)(o1 + (size_t)node * CC))[lane];
    float c0 = a0 * fmaxf(u.x, 0.f) + a1 * fmaxf(v.x, 0.f);
    float c1 = a0 * fmaxf(u.y, 0.f) + a1 * fmaxf(v.y, 0.f);
    float c2 = a0 * fmaxf(u.z, 0.f) + a1 * fmaxf(v.z, 0.f);
    float c3 = a0 * fmaxf(u.w, 0.f) + a1 * fmaxf(v.w, 0.f);
    const float* w = lw + lane * 4 * OUTD;
#pragma unroll
    for (int o = 0; o < OUTD; ++o) {
        float p = c0 * w[o] + c1 * w[OUTD + o] + c2 * w[2 * OUTD + o]
                + c3 * w[3 * OUTD + o];
#pragma unroll
        for (int off = 16; off > 0; off >>= 1)
            p += __shfl_xor_sync(0xffffffffu, p, off);
        if (lane == 0) out[(size_t)node * OUTD + o] = p + lb[o];
    }
}

// ---------------------------------------------------------------------------
// Host side
// ---------------------------------------------------------------------------
struct Scratch {
    float* h; float* out0; float* out1;
    float* asrc; float* adst; float* alpha;
    float* asum; float* colsum; float* attn;
};

#define NTILES ((NN + 127) / 128)

static void run_han_layer(const float* input, const float* input2, int Kin,
                          const float* pw, const float* pb,
                          const float* att_src, const float* att_dst,
                          const float* q, const float* kw, const float* kb,
                          const int* ei0, const int* ei1, const Scratch& S) {
    if (Kin == 64) {
        size_t sm = (64 * 128 + 128 * (64 + KPAD)) * 4;
        gemm_tf32_kernel<64, false><<<NTILES, 256, sm>>>(input, nullptr, nullptr,
                                                         pw, pb, S.h);
    } else {
        size_t sm = (128 * 128 + 128 * (128 + KPAD)) * 4;
        gemm_tf32_kernel<128, true><<<NTILES, 256, sm>>>(input, input2, S.attn,
                                                         pw, pb, S.h);
    }

    node_attn_kernel<<<(NN * 32 + 255) / 256, 256>>>(S.h, att_src, att_dst,
                                                     S.asrc, S.adst, NN);

    cudaMemsetAsync(S.colsum, 0, MT * CC * sizeof(float));

    const int* eis[2] = {ei0, ei1};
    float* outs[2] = {S.out0, S.out1};
    size_t sm_sem = (128 * 128 + 128 * (128 + KPAD)) * 4;
    for (int t = 0; t < MT; ++t) {
        cudaMemsetAsync(S.asum, 0, NN * HH * sizeof(float));
        cudaMemsetAsync(outs[t], 0, (size_t)NN * CC * sizeof(float));

        const float* asrc_t = S.asrc + t * (NN * HH);
        const float* adst_t = S.adst + t * (NN * HH);

        edge_softmax_kernel<<<(EE + 255) / 256, 256>>>(eis[t], asrc_t, adst_t,
                                                       S.alpha, S.asum);
        edge_message_kernel<<<(EE * 32 + 255) / 256, 256>>>(eis[t], S.alpha,
                                                            S.asum, S.h, outs[t]);
        semantic_tf32_kernel<<<NTILES, 256, sm_sem>>>(outs[t], kw, kb,
                                                      S.colsum + t * CC);
    }

    score_softmax_kernel<<<1, 128>>>(q, S.colsum, S.attn);
}

extern "C" void kernel_launch(void* const* d_in, const int* in_sizes, int n_in,
                              void* d_out, int out_size) {
    const float *x = nullptr, *p1w = nullptr;
    const float *b128[6] = {nullptr};
    const float *a256[4] = {nullptr};
    const float *w16384[3] = {nullptr};
    const float *lin_w = nullptr, *lin_b = nullptr;
    const int *ei[2] = {nullptr, nullptr};
    int n128 = 0, n256 = 0, n16384 = 0, nei = 0;

    for (int i = 0; i < n_in; ++i) {
        int sz = in_sizes[i];
        const void* p = d_in[i];
        switch (sz) {
            case NN * FIN:      x = (const float*)p; break;
            case 2 * EE:        if (nei < 2) ei[nei++] = (const int*)p; break;
            case FIN * CC:      p1w = (const float*)p; break;
            case CC * CC:       if (n16384 < 3) w16384[n16384++] = (const float*)p; break;
            case MT * HH * DD:  if (n256 < 4) a256[n256++] = (const float*)p; break;
            case CC:            if (n128 < 6) b128[n128++] = (const float*)p; break;
            case CC * OUTD:     lin_w = (const float*)p; break;
            case OUTD:          lin_b = (const float*)p; break;
            default: break;
        }
    }
    const float* p1_kw = w16384[0];
    const float* p2w   = w16384[1];
    const float* p2_kw = w16384[2];
    const float *p1_pb = b128[0], *p1_q = b128[1], *p1_kb = b128[2];
    const float *p2_pb = b128[3], *p2_q = b128[4], *p2_kb = b128[5];
    const float *p1_as = a256[0], *p1_ad = a256[1];
    const float *p2_as = a256[2], *p2_ad = a256[3];

    (void)cudaFuncSetAttribute(gemm_tf32_kernel<64, false>,
                               cudaFuncAttributeMaxDynamicSharedMemorySize, 160 * 1024);
    (void)cudaFuncSetAttribute(gemm_tf32_kernel<128, true>,
                               cudaFuncAttributeMaxDynamicSharedMemorySize, 160 * 1024);
    (void)cudaFuncSetAttribute(semantic_tf32_kernel,
                               cudaFuncAttributeMaxDynamicSharedMemorySize, 160 * 1024);

    Scratch S;
    cudaGetSymbolAddress((void**)&S.h, g_h);
    cudaGetSymbolAddress((void**)&S.out0, g_out0);
    cudaGetSymbolAddress((void**)&S.out1, g_out1);
    cudaGetSymbolAddress((void**)&S.asrc, g_asrc);
    cudaGetSymbolAddress((void**)&S.adst, g_adst);
    cudaGetSymbolAddress((void**)&S.alpha, g_alpha);
    cudaGetSymbolAddress((void**)&S.asum, g_asum);
    cudaGetSymbolAddress((void**)&S.colsum, g_colsum);
    cudaGetSymbolAddress((void**)&S.attn, g_attn);

    // Layer 1: IN=64 -> C=128
    run_han_layer(x, nullptr, 64, p1w, p1_pb, p1_as, p1_ad, p1_q, p1_kw, p1_kb,
                  ei[0], ei[1], S);
    // Layer 2: combine fused into projection A-load
    run_han_layer(S.out0, S.out1, 128, p2w, p2_pb, p2_as, p2_ad, p2_q, p2_kw,
                  p2_kb, ei[0], ei[1], S);

    // Final classifier (combine fused)
    final_linear_kernel<<<(NN * 32 + 255) / 256, 256>>>(
        S.out0, S.out1, S.attn, lin_w, lin_b, (float*)d_out);
}

// round 8
// speedup vs baseline: 1.4265x; 1.4265x over previous
#include <cuda_runtime.h>
#include <math.h>
#include <stdint.h>

// Problem constants
#define NN   100000
#define FIN  64
#define CC   128
#define HH   2
#define DD   64
#define EE   600000
#define MT   2
#define OUTD 8

// ---------------------------------------------------------------------------
// Scratch (device globals — no allocation allowed)
// ---------------------------------------------------------------------------
__device__ float    g_h[(size_t)NN * CC];
__device__ float    g_out0[(size_t)NN * CC];    // unnormalized segment sums
__device__ float    g_out1[(size_t)NN * CC];
__device__ float    g_asrc[MT * NN * HH];
__device__ float    g_adst[MT * NN * HH];
__device__ float    g_asum[MT * NN * HH];       // per-type exp sums
__device__ float    g_colsum[MT * CC];
__device__ float    g_attn[MT];

// ---------------------------------------------------------------------------
// Helpers
// ---------------------------------------------------------------------------
__device__ __forceinline__ uint64_t splat2(float x) {
    uint64_t r;
    asm("mov.b64 %0, {%1, %1};" : "=l"(r) : "f"(x));
    return r;
}
__device__ __forceinline__ void fma2(uint64_t& acc, uint64_t a, uint64_t b) {
    asm("fma.rn.f32x2 %0, %1, %2, %0;" : "+l"(acc) : "l"(a), "l"(b));
}
__device__ __forceinline__ float2 unpack2(uint64_t v) {
    float2 f;
    asm("mov.b64 {%0, %1}, %2;" : "=f"(f.x), "=f"(f.y) : "l"(v));
    return f;
}
__device__ __forceinline__ float tanh_fast(float x) {
    float y;
    asm("tanh.approx.f32 %0, %1;" : "=f"(y) : "f"(x));
    return y;
}
__device__ __forceinline__ void red_add_v4(float* p, float x, float y, float z, float w) {
    asm volatile("red.global.add.v4.f32 [%0], {%1,%2,%3,%4};"
                 :: "l"(p), "f"(x), "f"(y), "f"(z), "f"(w) : "memory");
}
__device__ __forceinline__ void red_add_v2(float* p, float x, float y) {
    asm volatile("red.global.add.v2.f32 [%0], {%1,%2};"
                 :: "l"(p), "f"(x), "f"(y) : "memory");
}

// ---------------------------------------------------------------------------
// Projection GEMM (R2 proven shape): out = A @ W + b
// 32-row tiles, 4x4 per-thread tile, persistent, W smem-resident, f32x2 FMA.
// FUSED (layer-2): A row := attn0*relu(o0)/s0 + attn1*relu(o1)/s1
//   (normalization of the unnormalized segment sums folded into the load)
// ---------------------------------------------------------------------------
template <int K, bool FUSED>
__global__ void gemm_proj_kernel(const float* __restrict__ A,
                                 const float* __restrict__ A2,
                                 const float* __restrict__ asum0,
                                 const float* __restrict__ asum1,
                                 const float* __restrict__ attn,
                                 const float* __restrict__ W,
                                 const float* __restrict__ b,
                                 float* __restrict__ out) {
    extern __shared__ float smem[];
    float* sW = smem;             // [K][128]
    float* sA = smem + K * 128;   // [32][K]
    const int tid = threadIdx.x;
    const int cg = tid & 31;
    const int rg = tid >> 5;

    for (int idx = tid; idx < K * 128; idx += 256) sW[idx] = W[idx];
    float4 b4 = *(const float4*)&b[cg * 4];
    float at0 = 0.f, at1 = 0.f;
    if (FUSED) { at0 = attn[0]; at1 = attn[1]; }

    const int ntiles = NN / 32;   // NN % 32 == 0
    for (int tile = blockIdx.x; tile < ntiles; tile += gridDim.x) {
        __syncthreads();
        const float4* Ab  = (const float4*)(A  + (size_t)tile * 32 * K);
        const float4* Ab2 = FUSED ? (const float4*)(A2 + (size_t)tile * 32 * K)
                                  : nullptr;
        for (int idx = tid; idx < 32 * (K / 4); idx += 256) {
            float4 v;
            if (FUSED) {
                int r = idx / (K / 4), k4 = idx % (K / 4);
                int node = tile * 32 + r;
                int head = (k4 * 4) / DD;   // cols 0..63 head0, 64..127 head1
                float i0 = at0 / (asum0[node * HH + head] + 1e-16f);
                float i1 = at1 / (asum1[node * HH + head] + 1e-16f);
                float4 u = Ab[idx], w = Ab2[idx];
                v.x = i0 * fmaxf(u.x, 0.f) + i1 * fmaxf(w.x, 0.f);
                v.y = i0 * fmaxf(u.y, 0.f) + i1 * fmaxf(w.y, 0.f);
                v.z = i0 * fmaxf(u.z, 0.f) + i1 * fmaxf(w.z, 0.f);
                v.w = i0 * fmaxf(u.w, 0.f) + i1 * fmaxf(w.w, 0.f);
            } else {
                v = Ab[idx];
            }
            ((float4*)sA)[idx] = v;
        }
        __syncthreads();

        uint64_t acc[4][2];
#pragma unroll
        for (int r = 0; r < 4; ++r) { acc[r][0] = 0ull; acc[r][1] = 0ull; }

#pragma unroll 2
        for (int k4 = 0; k4 < K; k4 += 4) {
            float4 a[4];
#pragma unroll
            for (int r = 0; r < 4; ++r)
                a[r] = *(const float4*)&sA[(4 * rg + r) * K + k4];
#pragma unroll
            for (int kk = 0; kk < 4; ++kk) {
                ulonglong2 wv = *(const ulonglong2*)&sW[(k4 + kk) * 128 + cg * 4];
#pragma unroll
                for (int r = 0; r < 4; ++r) {
                    float av = (kk == 0) ? a[r].x : (kk == 1) ? a[r].y
                             : (kk == 2) ? a[r].z : a[r].w;
                    uint64_t a2 = splat2(av);
                    fma2(acc[r][0], a2, wv.x);
                    fma2(acc[r][1], a2, wv.y);
                }
            }
        }
#pragma unroll
        for (int r = 0; r < 4; ++r) {
            float2 p0 = unpack2(acc[r][0]);
            float2 p1 = unpack2(acc[r][1]);
            float4 o = make_float4(p0.x + b4.x, p0.y + b4.y, p1.x + b4.z, p1.y + b4.w);
            int row = tile * 32 + 4 * rg + r;
            *(float4*)&out[(size_t)row * 128 + cg * 4] = o;
        }
    }
}

// ---------------------------------------------------------------------------
// Semantic GEMM (R2 proven shape):
// colsum[c] += sum_n tanh( (relu(out[n,:])/s) @ kw[:,c] + kb[c] )
// ---------------------------------------------------------------------------
__global__ void semantic_gemm_kernel(const float* __restrict__ A,
                                     const float* __restrict__ asum,
                                     const float* __restrict__ kw,
                                     const float* __restrict__ kb,
                                     float* __restrict__ colsum) {
    extern __shared__ float smem[];
    float* sW = smem;               // [128][128]
    float* sA = smem + 128 * 128;   // [32][128]
    __shared__ float scol[128];
    const int tid = threadIdx.x;
    const int cg = tid & 31;
    const int rg = tid >> 5;

    for (int idx = tid; idx < 128 * 128; idx += 256) sW[idx] = kw[idx];
    if (tid < 128) scol[tid] = 0.0f;
    float4 kb4 = *(const float4*)&kb[cg * 4];

    float tsum[4] = {0.f, 0.f, 0.f, 0.f};

    const int ntiles = NN / 32;
    for (int tile = blockIdx.x; tile < ntiles; tile += gridDim.x) {
        __syncthreads();
        const float4* Ab = (const float4*)(A + (size_t)tile * 32 * 128);
        for (int idx = tid; idx < 32 * 32; idx += 256) {
            int r = idx >> 5, k4 = idx & 31;
            int node = tile * 32 + r;
            int head = k4 >> 4;
            float inv = 1.0f / (asum[node * HH + head] + 1e-16f);
            float4 u = Ab[idx];
            float4 v = make_float4(fmaxf(u.x, 0.f) * inv, fmaxf(u.y, 0.f) * inv,
                                   fmaxf(u.z, 0.f) * inv, fmaxf(u.w, 0.f) * inv);
            ((float4*)sA)[idx] = v;
        }
        __syncthreads();

        uint64_t acc[4][2];
#pragma unroll
        for (int r = 0; r < 4; ++r) { acc[r][0] = 0ull; acc[r][1] = 0ull; }

#pragma unroll 2
        for (int k4 = 0; k4 < 128; k4 += 4) {
            float4 a[4];
#pragma unroll
            for (int r = 0; r < 4; ++r)
                a[r] = *(const float4*)&sA[(4 * rg + r) * 128 + k4];
#pragma unroll
            for (int kk = 0; kk < 4; ++kk) {
                ulonglong2 wv = *(const ulonglong2*)&sW[(k4 + kk) * 128 + cg * 4];
#pragma unroll
                for (int r = 0; r < 4; ++r) {
                    float av = (kk == 0) ? a[r].x : (kk == 1) ? a[r].y
                             : (kk == 2) ? a[r].z : a[r].w;
                    uint64_t a2 = splat2(av);
                    fma2(acc[r][0], a2, wv.x);
                    fma2(acc[r][1], a2, wv.y);
                }
            }
        }
#pragma unroll
        for (int r = 0; r < 4; ++r) {
            float2 p0 = unpack2(acc[r][0]);
            float2 p1 = unpack2(acc[r][1]);
            tsum[0] += tanh_fast(p0.x + kb4.x);
            tsum[1] += tanh_fast(p0.y + kb4.y);
            tsum[2] += tanh_fast(p1.x + kb4.z);
            tsum[3] += tanh_fast(p1.y + kb4.w);
        }
    }
    __syncthreads();
#pragma unroll
    for (int j = 0; j < 4; ++j) atomicAdd(&scol[cg * 4 + j], tsum[j]);
    __syncthreads();
    if (tid < 128) atomicAdd(&colsum[tid], scol[tid]);
}

// ---------------------------------------------------------------------------
// Per-node attention logits, warp per node
// ---------------------------------------------------------------------------
__global__ void node_attn_kernel(const float* __restrict__ h,
                                 const float* __restrict__ att_src,
                                 const float* __restrict__ att_dst,
                                 float* __restrict__ asrc,
                                 float* __restrict__ adst, int n) {
    int gid = blockIdx.x * blockDim.x + threadIdx.x;
    int node = gid >> 5;
    int lane = gid & 31;
    if (node >= n) return;
    const float* hrow = h + (size_t)node * CC;
    float h00 = hrow[lane];
    float h01 = hrow[lane + 32];
    float h10 = hrow[lane + 64];
    float h11 = hrow[lane + 96];

    float r[8];
#pragma unroll
    for (int t = 0; t < MT; ++t) {
        const float* as = att_src + t * CC;
        const float* ad = att_dst + t * CC;
        r[t * 4 + 0] = h00 * as[lane] + h01 * as[lane + 32];
        r[t * 4 + 1] = h10 * as[lane + 64] + h11 * as[lane + 96];
        r[t * 4 + 2] = h00 * ad[lane] + h01 * ad[lane + 32];
        r[t * 4 + 3] = h10 * ad[lane + 64] + h11 * ad[lane + 96];
    }
#pragma unroll
    for (int i = 0; i < 8; ++i) {
#pragma unroll
        for (int off = 16; off > 0; off >>= 1)
            r[i] += __shfl_xor_sync(0xffffffffu, r[i], off);
    }
    if (lane == 0) {
#pragma unroll
        for (int t = 0; t < MT; ++t) {
            asrc[t * (NN * HH) + node * HH + 0] = r[t * 4 + 0];
            asrc[t * (NN * HH) + node * HH + 1] = r[t * 4 + 1];
            adst[t * (NN * HH) + node * HH + 0] = r[t * 4 + 2];
            adst[t * (NN * HH) + node * HH + 1] = r[t * 4 + 3];
        }
    }
}

// ---------------------------------------------------------------------------
// Fused edge pass (softmax kernel eliminated):
//   e_h  = exp(leaky(asrc[src][h] + adst[dst][h]))   (shift-invariant softmax)
//   out[dst] += e_h * h[src]      (unnormalized, 32 lanes/edge, v4 red)
//   asum[dst][*] += (e0, e1)      (lane 0, v2 red)
// Normalization is linear and is folded into all consumers.
// ---------------------------------------------------------------------------
__global__ void edge_message_kernel(const int* __restrict__ ei,
                                    const float* __restrict__ asrc,
                                    const float* __restrict__ adst,
                                    const float* __restrict__ h,
                                    float* __restrict__ outT,
                                    float* __restrict__ asum) {
    int gid = blockIdx.x * blockDim.x + threadIdx.x;
    int e = gid >> 5;
    int lane = gid & 31;
    if (e >= EE) return;
    int src = ei[e];
    int dst = ei[EE + e];
    float2 s = *(const float2*)&asrc[src * HH];
    float2 d = *(const float2*)&adst[dst * HH];
    float a0 = s.x + d.x;
    float a1 = s.y + d.y;
    float l0 = (a0 > 0.0f) ? a0 : 0.2f * a0;
    float l1 = (a1 > 0.0f) ? a1 : 0.2f * a1;
    int head = lane >> 4;
    float mye = expf(head ? l1 : l0);          // one expf sequence per warp
    float4 v = ((const float4*)(h + (size_t)src * CC))[lane];
    red_add_v4(outT + (size_t)dst * CC + lane * 4,
               v.x * mye, v.y * mye, v.z * mye, v.w * mye);
    float e1 = __shfl_sync(0xffffffffu, mye, 16);
    if (lane == 0) red_add_v2(&asum[dst * HH], mye, e1);
}

// ---------------------------------------------------------------------------
// Semantic score + softmax (single block, 128 threads)
// ---------------------------------------------------------------------------
__global__ void score_softmax_kernel(const float* __restrict__ q,
                                     const float* __restrict__ colsum,
                                     float* __restrict__ attn) {
    __shared__ float red[128];
    int c = threadIdx.x;
    float s[MT];
#pragma unroll
    for (int m = 0; m < MT; ++m) {
        red[c] = q[c] * colsum[m * CC + c];
        __syncthreads();
        for (int off = 64; off > 0; off >>= 1) {
            if (c < off) red[c] += red[c + off];
            __syncthreads();
        }
        s[m] = red[0] * (1.0f / (float)NN);
        __syncthreads();
    }
    if (c == 0) {
        float mx = fmaxf(s[0], s[1]);
        float e0 = expf(s[0] - mx), e1 = expf(s[1] - mx);
        float inv = 1.0f / (e0 + e1);
        attn[0] = e0 * inv;
        attn[1] = e1 * inv;
    }
}

// ---------------------------------------------------------------------------
// Final linear fused with combine + normalization: warp per node
// ---------------------------------------------------------------------------
__global__ void final_linear_kernel(const float* __restrict__ o0,
                                    const float* __restrict__ o1,
                                    const float* __restrict__ asum0,
                                    const float* __restrict__ asum1,
                                    const float* __restrict__ attn,
                                    const float* __restrict__ lw,
                                    const float* __restrict__ lb,
                                    float* __restrict__ out) {
    int gid = blockIdx.x * blockDim.x + threadIdx.x;
    int node = gid >> 5;
    int lane = gid & 31;
    if (node >= NN) return;
    int head = lane >> 4;
    float i0 = attn[0] / (asum0[node * HH + head] + 1e-16f);
    float i1 = attn[1] / (asum1[node * HH + head] + 1e-16f);
    float4 u = ((const float4*)(o0 + (size_t)node * CC))[lane];
    float4 v = ((const float4*)(o1 + (size_t)node * CC))[lane];
    float c0 = i0 * fmaxf(u.x, 0.f) + i1 * fmaxf(v.x, 0.f);
    float c1 = i0 * fmaxf(u.y, 0.f) + i1 * fmaxf(v.y, 0.f);
    float c2 = i0 * fmaxf(u.z, 0.f) + i1 * fmaxf(v.z, 0.f);
    float c3 = i0 * fmaxf(u.w, 0.f) + i1 * fmaxf(v.w, 0.f);
    const float* w = lw + lane * 4 * OUTD;
#pragma unroll
    for (int o = 0; o < OUTD; ++o) {
        float p = c0 * w[o] + c1 * w[OUTD + o] + c2 * w[2 * OUTD + o]
                + c3 * w[3 * OUTD + o];
#pragma unroll
        for (int off = 16; off > 0; off >>= 1)
            p += __shfl_xor_sync(0xffffffffu, p, off);
        if (lane == 0) out[(size_t)node * OUTD + o] = p + lb[o];
    }
}

// ---------------------------------------------------------------------------
// Host side
// ---------------------------------------------------------------------------
struct Scratch {
    float* h; float* out0; float* out1;
    float* asrc; float* adst; float* asum;
    float* colsum; float* attn;
};

#define GEMM_BLOCKS 296

static void run_han_layer(const float* input, const float* input2, int Kin,
                          const float* pw, const float* pb,
                          const float* att_src, const float* att_dst,
                          const float* q, const float* kw, const float* kb,
                          const int* ei0, const int* ei1, const Scratch& S) {
    // asum from the PREVIOUS layer is consumed by the fused proj load.
    if (Kin == 64) {
        size_t sm = (64 * 128 + 32 * 64) * sizeof(float);
        gemm_proj_kernel<64, false><<<GEMM_BLOCKS, 256, sm>>>(
            input, nullptr, nullptr, nullptr, nullptr, pw, pb, S.h);
    } else {
        size_t sm = (128 * 128 + 32 * 128) * sizeof(float);
        gemm_proj_kernel<128, true><<<GEMM_BLOCKS, 256, sm>>>(
            input, input2, S.asum, S.asum + NN * HH, S.attn, pw, pb, S.h);
    }

    node_attn_kernel<<<(NN * 32 + 255) / 256, 256>>>(S.h, att_src, att_dst,
                                                     S.asrc, S.adst, NN);

    cudaMemsetAsync(S.colsum, 0, MT * CC * sizeof(float));
    cudaMemsetAsync(S.asum, 0, MT * NN * HH * sizeof(float));

    const int* eis[2] = {ei0, ei1};
    float* outs[2] = {S.out0, S.out1};
    size_t sm_sem = (128 * 128 + 32 * 128) * sizeof(float);
    for (int t = 0; t < MT; ++t) {
        cudaMemsetAsync(outs[t], 0, (size_t)NN * CC * sizeof(float));

        const float* asrc_t = S.asrc + t * (NN * HH);
        const float* adst_t = S.adst + t * (NN * HH);
        float* asum_t = S.asum + t * (NN * HH);

        edge_message_kernel<<<(EE * 32 + 255) / 256, 256>>>(
            eis[t], asrc_t, adst_t, S.h, outs[t], asum_t);
        semantic_gemm_kernel<<<GEMM_BLOCKS, 256, sm_sem>>>(
            outs[t], asum_t, kw, kb, S.colsum + t * CC);
    }

    score_softmax_kernel<<<1, 128>>>(q, S.colsum, S.attn);
}

extern "C" void kernel_launch(void* const* d_in, const int* in_sizes, int n_in,
                              void* d_out, int out_size) {
    const float *x = nullptr, *p1w = nullptr;
    const float *b128[6] = {nullptr};
    const float *a256[4] = {nullptr};
    const float *w16384[3] = {nullptr};
    const float *lin_w = nullptr, *lin_b = nullptr;
    const int *ei[2] = {nullptr, nullptr};
    int n128 = 0, n256 = 0, n16384 = 0, nei = 0;

    for (int i = 0; i < n_in; ++i) {
        int sz = in_sizes[i];
        const void* p = d_in[i];
        switch (sz) {
            case NN * FIN:      x = (const float*)p; break;
            case 2 * EE:        if (nei < 2) ei[nei++] = (const int*)p; break;
            case FIN * CC:      p1w = (const float*)p; break;
            case CC * CC:       if (n16384 < 3) w16384[n16384++] = (const float*)p; break;
            case MT * HH * DD:  if (n256 < 4) a256[n256++] = (const float*)p; break;
            case CC:            if (n128 < 6) b128[n128++] = (const float*)p; break;
            case CC * OUTD:     lin_w = (const float*)p; break;
            case OUTD:          lin_b = (const float*)p; break;
            default: break;
        }
    }
    const float* p1_kw = w16384[0];
    const float* p2w   = w16384[1];
    const float* p2_kw = w16384[2];
    const float *p1_pb = b128[0], *p1_q = b128[1], *p1_kb = b128[2];
    const float *p2_pb = b128[3], *p2_q = b128[4], *p2_kb = b128[5];
    const float *p1_as = a256[0], *p1_ad = a256[1];
    const float *p2_as = a256[2], *p2_ad = a256[3];

    (void)cudaFuncSetAttribute(gemm_proj_kernel<64, false>,
                               cudaFuncAttributeMaxDynamicSharedMemorySize, 100 * 1024);
    (void)cudaFuncSetAttribute(gemm_proj_kernel<128, true>,
                               cudaFuncAttributeMaxDynamicSharedMemorySize, 100 * 1024);
    (void)cudaFuncSetAttribute(semantic_gemm_kernel,
                               cudaFuncAttributeMaxDynamicSharedMemorySize, 100 * 1024);

    Scratch S;
    cudaGetSymbolAddress((void**)&S.h, g_h);
    cudaGetSymbolAddress((void**)&S.out0, g_out0);
    cudaGetSymbolAddress((void**)&S.out1, g_out1);
    cudaGetSymbolAddress((void**)&S.asrc, g_asrc);
    cudaGetSymbolAddress((void**)&S.adst, g_adst);
    cudaGetSymbolAddress((void**)&S.asum, g_asum);
    cudaGetSymbolAddress((void**)&S.colsum, g_colsum);
    cudaGetSymbolAddress((void**)&S.attn, g_attn);

    // Layer 1: IN=64 -> C=128
    run_han_layer(x, nullptr, 64, p1w, p1_pb, p1_as, p1_ad, p1_q, p1_kw, p1_kb,
                  ei[0], ei[1], S);
    // Layer 2: combine + normalization fused into projection A-load
    run_han_layer(S.out0, S.out1, 128, p2w, p2_pb, p2_as, p2_ad, p2_q, p2_kw,
                  p2_kb, ei[0], ei[1], S);

    // Final classifier (combine + normalization fused)
    final_linear_kernel<<<(NN * 32 + 255) / 256, 256>>>(
        S.out0, S.out1, S.asum, S.asum + NN * HH, S.attn, lin_w, lin_b,
        (float*)d_out);
}

// round 9
// speedup vs baseline: 1.4385x; 1.0084x over previous
#include <cuda_runtime.h>
#include <math.h>
#include <stdint.h>

// Problem constants
#define NN   100000
#define FIN  64
#define CC   128
#define HH   2
#define DD   64
#define EE   600000
#define MT   2
#define OUTD 8

// ---------------------------------------------------------------------------
// Scratch (device globals — no allocation allowed)
// ---------------------------------------------------------------------------
__device__ float    g_h[(size_t)NN * CC];
__device__ float    g_out0[(size_t)NN * CC];
__device__ float    g_out1[(size_t)NN * CC];
__device__ float    g_asrc[MT * NN * HH];
__device__ float    g_adst[MT * NN * HH];
__device__ float    g_alpha[(size_t)EE * HH];
__device__ float    g_asum[NN * HH];
__device__ float    g_colsum[MT * CC];
__device__ float    g_attn[MT];

// ---------------------------------------------------------------------------
// Helpers
// ---------------------------------------------------------------------------
__device__ __forceinline__ uint64_t splat2(float x) {
    uint64_t r;
    asm("mov.b64 %0, {%1, %1};" : "=l"(r) : "f"(x));
    return r;
}
__device__ __forceinline__ void fma2(uint64_t& acc, uint64_t a, uint64_t b) {
    asm("fma.rn.f32x2 %0, %1, %2, %0;" : "+l"(acc) : "l"(a), "l"(b));
}
__device__ __forceinline__ float2 unpack2(uint64_t v) {
    float2 f;
    asm("mov.b64 {%0, %1}, %2;" : "=f"(f.x), "=f"(f.y) : "l"(v));
    return f;
}
__device__ __forceinline__ float tanh_fast(float x) {
    float y;
    asm("tanh.approx.f32 %0, %1;" : "=f"(y) : "f"(x));
    return y;
}
__device__ __forceinline__ void red_add_v4(float* p, float x, float y, float z, float w) {
    asm volatile("red.global.add.v4.f32 [%0], {%1,%2,%3,%4};"
                 :: "l"(p), "f"(x), "f"(y), "f"(z), "f"(w) : "memory");
}
__device__ __forceinline__ void red_add_v2(float* p, float x, float y) {
    asm volatile("red.global.add.v2.f32 [%0], {%1,%2};"
                 :: "l"(p), "f"(x), "f"(y) : "memory");
}

// ---------------------------------------------------------------------------
// Projection GEMM: out = A @ W + b
// 64-row tiles, 8 rows x 4 cols per thread, persistent, W smem-resident.
// (vs R2's 4x4/32-row: halves W crossbar traffic per FLOP; 96KB smem keeps
//  2 blocks/SM = 16 warps, unlike R3's failed 1-block/SM 8x8.)
// FUSED (layer-2): A row := attn0*relu(o0) + attn1*relu(o1)
// ---------------------------------------------------------------------------
template <int K, bool FUSED>
__global__ void gemm_proj_kernel(const float* __restrict__ A,
                                 const float* __restrict__ A2,
                                 const float* __restrict__ attn,
                                 const float* __restrict__ W,
                                 const float* __restrict__ b,
                                 float* __restrict__ out) {
    extern __shared__ float smem[];
    float* sW = smem;             // [K][128]
    float* sA = smem + K * 128;   // [64][K]
    const int tid = threadIdx.x;
    const int cg = tid & 31;      // cols 4cg..4cg+3
    const int rg = tid >> 5;      // warp: rows 8rg..8rg+7 within tile

    for (int idx = tid; idx < K * 128; idx += 256) sW[idx] = W[idx];
    float4 b4 = *(const float4*)&b[cg * 4];
    float at0 = 0.f, at1 = 0.f;
    if (FUSED) { at0 = attn[0]; at1 = attn[1]; }

    const int ntiles = (NN + 63) / 64;
    for (int tile = blockIdx.x; tile < ntiles; tile += gridDim.x) {
        __syncthreads();
        const int rowbase = tile * 64;
        const float4* Ab  = (const float4*)(A  + (size_t)rowbase * K);
        const float4* Ab2 = FUSED ? (const float4*)(A2 + (size_t)rowbase * K)
                                  : nullptr;
        for (int idx = tid; idx < 64 * (K / 4); idx += 256) {
            int r = idx / (K / 4);
            float4 v = make_float4(0.f, 0.f, 0.f, 0.f);
            if (rowbase + r < NN) {
                if (FUSED) {
                    float4 u = Ab[idx], w = Ab2[idx];
                    v.x = at0 * fmaxf(u.x, 0.f) + at1 * fmaxf(w.x, 0.f);
                    v.y = at0 * fmaxf(u.y, 0.f) + at1 * fmaxf(w.y, 0.f);
                    v.z = at0 * fmaxf(u.z, 0.f) + at1 * fmaxf(w.z, 0.f);
                    v.w = at0 * fmaxf(u.w, 0.f) + at1 * fmaxf(w.w, 0.f);
                } else {
                    v = Ab[idx];
                }
            }
            ((float4*)sA)[idx] = v;
        }
        __syncthreads();

        uint64_t acc[8][2];
#pragma unroll
        for (int r = 0; r < 8; ++r) { acc[r][0] = 0ull; acc[r][1] = 0ull; }

#pragma unroll 2
        for (int k4 = 0; k4 < K; k4 += 4) {
            float4 a[8];
#pragma unroll
            for (int r = 0; r < 8; ++r)
                a[r] = *(const float4*)&sA[(8 * rg + r) * K + k4];
#pragma unroll
            for (int kk = 0; kk < 4; ++kk) {
                ulonglong2 wv = *(const ulonglong2*)&sW[(k4 + kk) * 128 + cg * 4];
#pragma unroll
                for (int r = 0; r < 8; ++r) {
                    float av = (kk == 0) ? a[r].x : (kk == 1) ? a[r].y
                             : (kk == 2) ? a[r].z : a[r].w;
                    uint64_t a2 = splat2(av);
                    fma2(acc[r][0], a2, wv.x);
                    fma2(acc[r][1], a2, wv.y);
                }
            }
        }
#pragma unroll
        for (int r = 0; r < 8; ++r) {
            int row = rowbase + 8 * rg + r;
            if (row < NN) {
                float2 p0 = unpack2(acc[r][0]);
                float2 p1 = unpack2(acc[r][1]);
                float4 o = make_float4(p0.x + b4.x, p0.y + b4.y,
                                       p1.x + b4.z, p1.y + b4.w);
                *(float4*)&out[(size_t)row * 128 + cg * 4] = o;
            }
        }
    }
}

// ---------------------------------------------------------------------------
// Semantic GEMM: colsum[c] += sum_n tanh( relu(A[n,:]) @ kw[:,c] + kb[c] )
// Same 8x4 / 64-row tiling; relu on A load; tanh.approx epilogue.
// ---------------------------------------------------------------------------
__global__ void semantic_gemm_kernel(const float* __restrict__ A,
                                     const float* __restrict__ kw,
                                     const float* __restrict__ kb,
                                     float* __restrict__ colsum) {
    extern __shared__ float smem[];
    float* sW = smem;               // [128][128]
    float* sA = smem + 128 * 128;   // [64][128]
    __shared__ float scol[128];
    const int tid = threadIdx.x;
    const int cg = tid & 31;
    const int rg = tid >> 5;

    for (int idx = tid; idx < 128 * 128; idx += 256) sW[idx] = kw[idx];
    if (tid < 128) scol[tid] = 0.0f;
    float4 kb4 = *(const float4*)&kb[cg * 4];

    float tsum[4] = {0.f, 0.f, 0.f, 0.f};

    const int ntiles = (NN + 63) / 64;
    for (int tile = blockIdx.x; tile < ntiles; tile += gridDim.x) {
        __syncthreads();
        const int rowbase = tile * 64;
        const float4* Ab = (const float4*)(A + (size_t)rowbase * 128);
        for (int idx = tid; idx < 64 * 32; idx += 256) {
            int r = idx >> 5;
            float4 v = make_float4(0.f, 0.f, 0.f, 0.f);
            if (rowbase + r < NN) {
                float4 u = Ab[idx];
                v = make_float4(fmaxf(u.x, 0.f), fmaxf(u.y, 0.f),
                                fmaxf(u.z, 0.f), fmaxf(u.w, 0.f));
            }
            ((float4*)sA)[idx] = v;
        }
        __syncthreads();

        uint64_t acc[8][2];
#pragma unroll
        for (int r = 0; r < 8; ++r) { acc[r][0] = 0ull; acc[r][1] = 0ull; }

#pragma unroll 2
        for (int k4 = 0; k4 < 128; k4 += 4) {
            float4 a[8];
#pragma unroll
            for (int r = 0; r < 8; ++r)
                a[r] = *(const float4*)&sA[(8 * rg + r) * 128 + k4];
#pragma unroll
            for (int kk = 0; kk < 4; ++kk) {
                ulonglong2 wv = *(const ulonglong2*)&sW[(k4 + kk) * 128 + cg * 4];
#pragma unroll
                for (int r = 0; r < 8; ++r) {
                    float av = (kk == 0) ? a[r].x : (kk == 1) ? a[r].y
                             : (kk == 2) ? a[r].z : a[r].w;
                    uint64_t a2 = splat2(av);
                    fma2(acc[r][0], a2, wv.x);
                    fma2(acc[r][1], a2, wv.y);
                }
            }
        }
#pragma unroll
        for (int r = 0; r < 8; ++r) {
            if (rowbase + 8 * rg + r < NN) {
                float2 p0 = unpack2(acc[r][0]);
                float2 p1 = unpack2(acc[r][1]);
                tsum[0] += tanh_fast(p0.x + kb4.x);
                tsum[1] += tanh_fast(p0.y + kb4.y);
                tsum[2] += tanh_fast(p1.x + kb4.z);
                tsum[3] += tanh_fast(p1.y + kb4.w);
            }
        }
    }
    __syncthreads();
#pragma unroll
    for (int j = 0; j < 4; ++j) atomicAdd(&scol[cg * 4 + j], tsum[j]);
    __syncthreads();
    if (tid < 128) atomicAdd(&colsum[tid], scol[tid]);
}

// ---------------------------------------------------------------------------
// Per-node attention logits, warp per node
// ---------------------------------------------------------------------------
__global__ void node_attn_kernel(const float* __restrict__ h,
                                 const float* __restrict__ att_src,
                                 const float* __restrict__ att_dst,
                                 float* __restrict__ asrc,
                                 float* __restrict__ adst, int n) {
    int gid = blockIdx.x * blockDim.x + threadIdx.x;
    int node = gid >> 5;
    int lane = gid & 31;
    if (node >= n) return;
    const float* hrow = h + (size_t)node * CC;
    float h00 = hrow[lane];
    float h01 = hrow[lane + 32];
    float h10 = hrow[lane + 64];
    float h11 = hrow[lane + 96];

    float r[8];
#pragma unroll
    for (int t = 0; t < MT; ++t) {
        const float* as = att_src + t * CC;
        const float* ad = att_dst + t * CC;
        r[t * 4 + 0] = h00 * as[lane] + h01 * as[lane + 32];
        r[t * 4 + 1] = h10 * as[lane + 64] + h11 * as[lane + 96];
        r[t * 4 + 2] = h00 * ad[lane] + h01 * ad[lane + 32];
        r[t * 4 + 3] = h10 * ad[lane + 64] + h11 * ad[lane + 96];
    }
#pragma unroll
    for (int i = 0; i < 8; ++i) {
#pragma unroll
        for (int off = 16; off > 0; off >>= 1)
            r[i] += __shfl_xor_sync(0xffffffffu, r[i], off);
    }
    if (lane == 0) {
#pragma unroll
        for (int t = 0; t < MT; ++t) {
            asrc[t * (NN * HH) + node * HH + 0] = r[t * 4 + 0];
            asrc[t * (NN * HH) + node * HH + 1] = r[t * 4 + 1];
            adst[t * (NN * HH) + node * HH + 0] = r[t * 4 + 2];
            adst[t * (NN * HH) + node * HH + 1] = r[t * 4 + 3];
        }
    }
}

// ---------------------------------------------------------------------------
// Edge softmax (R2/R3 measured path, 1 thread/edge):
// alpha = exp(leaky(asrc[src]+adst[dst])); asum[dst] += alpha
// (shift-invariant softmax, bounded logits — validated R3/R4/R8)
// ---------------------------------------------------------------------------
__global__ void edge_softmax_kernel(const int* __restrict__ ei,
                                    const float* __restrict__ asrc,
                                    const float* __restrict__ adst,
                                    float* __restrict__ alpha,
                                    float* __restrict__ asum) {
    int e = blockIdx.x * blockDim.x + threadIdx.x;
    if (e >= EE) return;
    int src = ei[e];
    int dst = ei[EE + e];
    float2 s = *(const float2*)&asrc[src * HH];
    float2 d = *(const float2*)&adst[dst * HH];
    float a0 = s.x + d.x;
    float a1 = s.y + d.y;
    float l0 = (a0 > 0.0f) ? a0 : 0.2f * a0;
    float l1 = (a1 > 0.0f) ? a1 : 0.2f * a1;
    float ex0 = expf(l0);
    float ex1 = expf(l1);
    *(float2*)&alpha[(size_t)e * HH] = make_float2(ex0, ex1);
    red_add_v2(&asum[dst * HH], ex0, ex1);
}

// ---------------------------------------------------------------------------
// Edge message (R2 measured path): out[dst] += h[src]*coef  (32 lanes/edge)
// ---------------------------------------------------------------------------
__global__ void edge_message_kernel(const int* __restrict__ ei,
                                    const float* __restrict__ expalpha,
                                    const float* __restrict__ asum,
                                    const float* __restrict__ h,
                                    float* __restrict__ outT) {
    int gid = blockIdx.x * blockDim.x + threadIdx.x;
    int e = gid >> 5;
    int lane = gid & 31;
    if (e >= EE) return;
    int src = ei[e];
    int dst = ei[EE + e];
    int head = lane >> 4;
    float coef = expalpha[(size_t)e * HH + head] /
                 (asum[dst * HH + head] + 1e-16f);
    const float4* hrow = reinterpret_cast<const float4*>(h + (size_t)src * CC);
    float4 v = hrow[lane];
    float* o = outT + (size_t)dst * CC + lane * 4;
    red_add_v4(o, v.x * coef, v.y * coef, v.z * coef, v.w * coef);
}

// ---------------------------------------------------------------------------
// Semantic score + softmax (single block, 128 threads)
// ---------------------------------------------------------------------------
__global__ void score_softmax_kernel(const float* __restrict__ q,
                                     const float* __restrict__ colsum,
                                     float* __restrict__ attn) {
    __shared__ float red[128];
    int c = threadIdx.x;
    float s[MT];
#pragma unroll
    for (int m = 0; m < MT; ++m) {
        red[c] = q[c] * colsum[m * CC + c];
        __syncthreads();
        for (int off = 64; off > 0; off >>= 1) {
            if (c < off) red[c] += red[c + off];
            __syncthreads();
        }
        s[m] = red[0] * (1.0f / (float)NN);
        __syncthreads();
    }
    if (c == 0) {
        float mx = fmaxf(s[0], s[1]);
        float e0 = expf(s[0] - mx), e1 = expf(s[1] - mx);
        float inv = 1.0f / (e0 + e1);
        attn[0] = e0 * inv;
        attn[1] = e1 * inv;
    }
}

// ---------------------------------------------------------------------------
// Final linear fused with combine: warp per node
// ---------------------------------------------------------------------------
__global__ void final_linear_kernel(const float* __restrict__ o0,
                                    const float* __restrict__ o1,
                                    const float* __restrict__ attn,
                                    const float* __restrict__ lw,
                                    const float* __restrict__ lb,
                                    float* __restrict__ out) {
    int gid = blockIdx.x * blockDim.x + threadIdx.x;
    int node = gid >> 5;
    int lane = gid & 31;
    if (node >= NN) return;
    float a0 = attn[0], a1 = attn[1];
    float4 u = ((const float4*)(o0 + (size_t)node * CC))[lane];
    float4 v = ((const float4*)(o1 + (size_t)node * CC))[lane];
    float c0 = a0 * fmaxf(u.x, 0.f) + a1 * fmaxf(v.x, 0.f);
    float c1 = a0 * fmaxf(u.y, 0.f) + a1 * fmaxf(v.y, 0.f);
    float c2 = a0 * fmaxf(u.z, 0.f) + a1 * fmaxf(v.z, 0.f);
    float c3 = a0 * fmaxf(u.w, 0.f) + a1 * fmaxf(v.w, 0.f);
    const float* w = lw + lane * 4 * OUTD;
#pragma unroll
    for (int o = 0; o < OUTD; ++o) {
        float p = c0 * w[o] + c1 * w[OUTD + o] + c2 * w[2 * OUTD + o]
                + c3 * w[3 * OUTD + o];
#pragma unroll
        for (int off = 16; off > 0; off >>= 1)
            p += __shfl_xor_sync(0xffffffffu, p, off);
        if (lane == 0) out[(size_t)node * OUTD + o] = p + lb[o];
    }
}

// ---------------------------------------------------------------------------
// Host side
// ---------------------------------------------------------------------------
struct Scratch {
    float* h; float* out0; float* out1;
    float* asrc; float* adst; float* alpha;
    float* asum; float* colsum; float* attn;
};

#define GEMM_BLOCKS 296

static void run_han_layer(const float* input, const float* input2, int Kin,
                          const float* pw, const float* pb,
                          const float* att_src, const float* att_dst,
                          const float* q, const float* kw, const float* kb,
                          const int* ei0, const int* ei1, const Scratch& S) {
    if (Kin == 64) {
        size_t sm = (64 * 128 + 64 * 64) * sizeof(float);
        gemm_proj_kernel<64, false><<<GEMM_BLOCKS, 256, sm>>>(
            input, nullptr, nullptr, pw, pb, S.h);
    } else {
        size_t sm = (128 * 128 + 64 * 128) * sizeof(float);
        gemm_proj_kernel<128, true><<<GEMM_BLOCKS, 256, sm>>>(
            input, input2, S.attn, pw, pb, S.h);
    }

    node_attn_kernel<<<(NN * 32 + 255) / 256, 256>>>(S.h, att_src, att_dst,
                                                     S.asrc, S.adst, NN);

    cudaMemsetAsync(S.colsum, 0, MT * CC * sizeof(float));

    const int* eis[2] = {ei0, ei1};
    float* outs[2] = {S.out0, S.out1};
    size_t sm_sem = (128 * 128 + 64 * 128) * sizeof(float);
    for (int t = 0; t < MT; ++t) {
        cudaMemsetAsync(S.asum, 0, NN * HH * sizeof(float));
        cudaMemsetAsync(outs[t], 0, (size_t)NN * CC * sizeof(float));

        const float* asrc_t = S.asrc + t * (NN * HH);
        const float* adst_t = S.adst + t * (NN * HH);

        edge_softmax_kernel<<<(EE + 255) / 256, 256>>>(eis[t], asrc_t, adst_t,
                                                       S.alpha, S.asum);
        edge_message_kernel<<<(EE * 32 + 255) / 256, 256>>>(eis[t], S.alpha,
                                                            S.asum, S.h, outs[t]);
        semantic_gemm_kernel<<<GEMM_BLOCKS, 256, sm_sem>>>(outs[t], kw, kb,
                                                           S.colsum + t * CC);
    }

    score_softmax_kernel<<<1, 128>>>(q, S.colsum, S.attn);
}

extern "C" void kernel_launch(void* const* d_in, const int* in_sizes, int n_in,
                              void* d_out, int out_size) {
    const float *x = nullptr, *p1w = nullptr;
    const float *b128[6] = {nullptr};
    const float *a256[4] = {nullptr};
    const float *w16384[3] = {nullptr};
    const float *lin_w = nullptr, *lin_b = nullptr;
    const int *ei[2] = {nullptr, nullptr};
    int n128 = 0, n256 = 0, n16384 = 0, nei = 0;

    for (int i = 0; i < n_in; ++i) {
        int sz = in_sizes[i];
        const void* p = d_in[i];
        switch (sz) {
            case NN * FIN:      x = (const float*)p; break;
            case 2 * EE:        if (nei < 2) ei[nei++] = (const int*)p; break;
            case FIN * CC:      p1w = (const float*)p; break;
            case CC * CC:       if (n16384 < 3) w16384[n16384++] = (const float*)p; break;
            case MT * HH * DD:  if (n256 < 4) a256[n256++] = (const float*)p; break;
            case CC:            if (n128 < 6) b128[n128++] = (const float*)p; break;
            case CC * OUTD:     lin_w = (const float*)p; break;
            case OUTD:          lin_b = (const float*)p; break;
            default: break;
        }
    }
    const float* p1_kw = w16384[0];
    const float* p2w   = w16384[1];
    const float* p2_kw = w16384[2];
    const float *p1_pb = b128[0], *p1_q = b128[1], *p1_kb = b128[2];
    const float *p2_pb = b128[3], *p2_q = b128[4], *p2_kb = b128[5];
    const float *p1_as = a256[0], *p1_ad = a256[1];
    const float *p2_as = a256[2], *p2_ad = a256[3];

    (void)cudaFuncSetAttribute(gemm_proj_kernel<64, false>,
                               cudaFuncAttributeMaxDynamicSharedMemorySize, 114 * 1024);
    (void)cudaFuncSetAttribute(gemm_proj_kernel<128, true>,
                               cudaFuncAttributeMaxDynamicSharedMemorySize, 114 * 1024);
    (void)cudaFuncSetAttribute(semantic_gemm_kernel,
                               cudaFuncAttributeMaxDynamicSharedMemorySize, 114 * 1024);

    Scratch S;
    cudaGetSymbolAddress((void**)&S.h, g_h);
    cudaGetSymbolAddress((void**)&S.out0, g_out0);
    cudaGetSymbolAddress((void**)&S.out1, g_out1);
    cudaGetSymbolAddress((void**)&S.asrc, g_asrc);
    cudaGetSymbolAddress((void**)&S.adst, g_adst);
    cudaGetSymbolAddress((void**)&S.alpha, g_alpha);
    cudaGetSymbolAddress((void**)&S.asum, g_asum);
    cudaGetSymbolAddress((void**)&S.colsum, g_colsum);
    cudaGetSymbolAddress((void**)&S.attn, g_attn);

    // Layer 1: IN=64 -> C=128
    run_han_layer(x, nullptr, 64, p1w, p1_pb, p1_as, p1_ad, p1_q, p1_kw, p1_kb,
                  ei[0], ei[1], S);
    // Layer 2: combine fused into projection A-load
    run_han_layer(S.out0, S.out1, 128, p2w, p2_pb, p2_as, p2_ad, p2_q, p2_kw,
                  p2_kb, ei[0], ei[1], S);

    // Final classifier (combine fused)
    final_linear_kernel<<<(NN * 32 + 255) / 256, 256>>>(
        S.out0, S.out1, S.attn, lin_w, lin_b, (float*)d_out);
}

// round 10
// speedup vs baseline: 1.5510x; 1.0782x over previous
#include <cuda_runtime.h>
#include <math.h>
#include <stdint.h>

// Problem constants
#define NN   100000
#define FIN  64
#define CC   128
#define HH   2
#define DD   64
#define EE   600000
#define MT   2
#define OUTD 8

// ---------------------------------------------------------------------------
// Scratch (device globals — no allocation allowed)
// ---------------------------------------------------------------------------
__device__ float    g_h[(size_t)NN * CC];
__device__ float    g_out0[(size_t)NN * CC];
__device__ float    g_out1[(size_t)NN * CC];
__device__ float    g_asrc[MT * NN * HH];
__device__ float    g_adst[MT * NN * HH];
__device__ float    g_alpha[(size_t)EE * HH];
__device__ float    g_asum[NN * HH];
__device__ float    g_colsum[MT * CC];
__device__ float    g_attn[MT];

// ---------------------------------------------------------------------------
// Helpers
// ---------------------------------------------------------------------------
__device__ __forceinline__ uint64_t splat2(float x) {
    uint64_t r;
    asm("mov.b64 %0, {%1, %1};" : "=l"(r) : "f"(x));
    return r;
}
__device__ __forceinline__ void fma2(uint64_t& acc, uint64_t a, uint64_t b) {
    asm("fma.rn.f32x2 %0, %1, %2, %0;" : "+l"(acc) : "l"(a), "l"(b));
}
__device__ __forceinline__ float2 unpack2(uint64_t v) {
    float2 f;
    asm("mov.b64 {%0, %1}, %2;" : "=f"(f.x), "=f"(f.y) : "l"(v));
    return f;
}
__device__ __forceinline__ float tanh_fast(float x) {
    float y;
    asm("tanh.approx.f32 %0, %1;" : "=f"(y) : "f"(x));
    return y;
}
__device__ __forceinline__ void red_add_v4(float* p, float x, float y, float z, float w) {
    asm volatile("red.global.add.v4.f32 [%0], {%1,%2,%3,%4};"
                 :: "l"(p), "f"(x), "f"(y), "f"(z), "f"(w) : "memory");
}
__device__ __forceinline__ void red_add_v2(float* p, float x, float y) {
    asm volatile("red.global.add.v2.f32 [%0], {%1,%2};"
                 :: "l"(p), "f"(x), "f"(y) : "memory");
}
__device__ __forceinline__ float f2tf32f(float f) {
    uint32_t u;
    asm("cvt.rna.tf32.f32 %0, %1;" : "=r"(u) : "f"(f));
    return __uint_as_float(u);
}
__device__ __forceinline__ void mma_tf32(float& c0, float& c1, float& c2, float& c3,
                                         uint32_t a0, uint32_t a1, uint32_t a2, uint32_t a3,
                                         uint32_t b0, uint32_t b1) {
    asm volatile(
        "mma.sync.aligned.m16n8k8.row.col.f32.tf32.tf32.f32 "
        "{%0,%1,%2,%3}, {%4,%5,%6,%7}, {%8,%9}, {%0,%1,%2,%3};"
        : "+f"(c0), "+f"(c1), "+f"(c2), "+f"(c3)
        : "r"(a0), "r"(a1), "r"(a2), "r"(a3), "r"(b0), "r"(b1));
}

// ---------------------------------------------------------------------------
// Projection GEMM (R2/R4 measured shape): out = A @ W + b
// 32-row tiles, 4x4 per-thread, persistent, W smem-resident, f32x2 FMA.
// FUSED (layer-2): A row := attn0*relu(o0) + attn1*relu(o1)
// ---------------------------------------------------------------------------
template <int K, bool FUSED>
__global__ void gemm_proj_kernel(const float* __restrict__ A,
                                 const float* __restrict__ A2,
                                 const float* __restrict__ attn,
                                 const float* __restrict__ W,
                                 const float* __restrict__ b,
                                 float* __restrict__ out) {
    extern __shared__ float smem[];
    float* sW = smem;             // [K][128]
    float* sA = smem + K * 128;   // [32][K]
    const int tid = threadIdx.x;
    const int cg = tid & 31;
    const int rg = tid >> 5;

    for (int idx = tid; idx < K * 128; idx += 256) sW[idx] = W[idx];
    float4 b4 = *(const float4*)&b[cg * 4];
    float at0 = 0.f, at1 = 0.f;
    if (FUSED) { at0 = attn[0]; at1 = attn[1]; }

    const int ntiles = NN / 32;   // NN % 32 == 0
    for (int tile = blockIdx.x; tile < ntiles; tile += gridDim.x) {
        __syncthreads();
        const float4* Ab  = (const float4*)(A  + (size_t)tile * 32 * K);
        const float4* Ab2 = FUSED ? (const float4*)(A2 + (size_t)tile * 32 * K)
                                  : nullptr;
        for (int idx = tid; idx < 32 * (K / 4); idx += 256) {
            float4 v;
            if (FUSED) {
                float4 u = Ab[idx], w = Ab2[idx];
                v.x = at0 * fmaxf(u.x, 0.f) + at1 * fmaxf(w.x, 0.f);
                v.y = at0 * fmaxf(u.y, 0.f) + at1 * fmaxf(w.y, 0.f);
                v.z = at0 * fmaxf(u.z, 0.f) + at1 * fmaxf(w.z, 0.f);
                v.w = at0 * fmaxf(u.w, 0.f) + at1 * fmaxf(w.w, 0.f);
            } else {
                v = Ab[idx];
            }
            ((float4*)sA)[idx] = v;
        }
        __syncthreads();

        uint64_t acc[4][2];
#pragma unroll
        for (int r = 0; r < 4; ++r) { acc[r][0] = 0ull; acc[r][1] = 0ull; }

#pragma unroll 2
        for (int k4 = 0; k4 < K; k4 += 4) {
            float4 a[4];
#pragma unroll
            for (int r = 0; r < 4; ++r)
                a[r] = *(const float4*)&sA[(4 * rg + r) * K + k4];
#pragma unroll
            for (int kk = 0; kk < 4; ++kk) {
                ulonglong2 wv = *(const ulonglong2*)&sW[(k4 + kk) * 128 + cg * 4];
#pragma unroll
                for (int r = 0; r < 4; ++r) {
                    float av = (kk == 0) ? a[r].x : (kk == 1) ? a[r].y
                             : (kk == 2) ? a[r].z : a[r].w;
                    uint64_t a2 = splat2(av);
                    fma2(acc[r][0], a2, wv.x);
                    fma2(acc[r][1], a2, wv.y);
                }
            }
        }
#pragma unroll
        for (int r = 0; r < 4; ++r) {
            float2 p0 = unpack2(acc[r][0]);
            float2 p1 = unpack2(acc[r][1]);
            float4 o = make_float4(p0.x + b4.x, p0.y + b4.y, p1.x + b4.z, p1.y + b4.w);
            int row = tile * 32 + 4 * rg + r;
            *(float4*)&out[(size_t)row * 128 + cg * 4] = o;
        }
    }
}

// ---------------------------------------------------------------------------
// Semantic GEMM, tf32 tensor cores with fragment-major W staging.
// colsum[c] += sum_n tanh( relu(A[n,:]) @ kw[:,c] + kb[c] )
//
// Per-block tile: 64 rows x 128 cols, K=128. 8 warps: warp w ->
// row-tile rt=w%4 (16 rows), col-half ch=w/4 (8 n-tiles of 8 cols).
// W staged ONCE per persistent block in m16n8k8 fragment order:
//   element (k,n): kstep=k/8, nt=n/8, lane=(n%8)*4+(k%4), slot=(k%8)/4
//   sWf[((kstep*16+nt)*32+lane)*2+slot]
// Compute: per kstep = 4 scalar A LDS + 8 float2 W LDS for 8 MMAs.
// A staged row-major (stride 132, conflict-free scalar reads), tf32-converted.
// smem = 64KB (sWf) + 33KB (sA) = 97KB -> 2 blocks/SM.
// ---------------------------------------------------------------------------
#define SEM_TILES ((NN + 63) / 64)
__global__ void __launch_bounds__(256)
semantic_tf32_kernel(const float* __restrict__ A,
                     const float* __restrict__ kw,
                     const float* __restrict__ kb,
                     float* __restrict__ colsum) {
    extern __shared__ float smem[];
    float* sWf = smem;            // 16384 floats
    float* sA  = smem + 16384;    // [64][132] = 8448 floats
    __shared__ float scol[128];
    const int tid  = threadIdx.x;
    const int lane = tid & 31;
    const int warp = tid >> 5;
    const int g4   = lane >> 2;   // groupID 0..7
    const int tig  = lane & 3;    // thread-in-group
    const int rt   = warp & 3;    // 16-row tile within 64
    const int ch   = warp >> 2;   // column half (0/1)

    // Stage W fragments once (reused across all persistent tiles)
    for (int i4 = tid; i4 < 4096; i4 += 256) {
        int k  = i4 >> 5;
        int n0 = (i4 & 31) * 4;
        float4 w4 = ((const float4*)kw)[i4];
        float wv[4] = {w4.x, w4.y, w4.z, w4.w};
        int ks = k >> 3;
        int slot = (k & 7) >> 2;
        int km = k & 3;
#pragma unroll
        for (int j = 0; j < 4; ++j) {
            int n = n0 + j;
            int nt = n >> 3;
            int ln = (n & 7) * 4 + km;
            sWf[(((ks * 16) + nt) * 32 + ln) * 2 + slot] = f2tf32f(wv[j]);
        }
    }
    if (tid < 128) scol[tid] = 0.0f;

    // kb for this thread's columns: col = (ch*8+nl)*8 + tig*2 (+0,+1)
    float2 kbv[8];
#pragma unroll
    for (int nl = 0; nl < 8; ++nl)
        kbv[nl] = *(const float2*)&kb[(ch * 8 + nl) * 8 + tig * 2];

    float tloc[8][2];
#pragma unroll
    for (int nl = 0; nl < 8; ++nl) { tloc[nl][0] = 0.f; tloc[nl][1] = 0.f; }

    for (int tile = blockIdx.x; tile < SEM_TILES; tile += gridDim.x) {
        __syncthreads();
        const int rowbase = tile * 64;
        const float4* Ab = (const float4*)(A + (size_t)rowbase * 128);
        for (int i4 = tid; i4 < 2048; i4 += 256) {
            int r = i4 >> 5, k4 = i4 & 31;
            float4 v = make_float4(0.f, 0.f, 0.f, 0.f);
            if (rowbase + r < NN) {
                float4 u = Ab[i4];
                v.x = f2tf32f(fmaxf(u.x, 0.f));
                v.y = f2tf32f(fmaxf(u.y, 0.f));
                v.z = f2tf32f(fmaxf(u.z, 0.f));
                v.w = f2tf32f(fmaxf(u.w, 0.f));
            }
            float* dst = &sA[r * 132 + k4 * 4];
            dst[0] = v.x; dst[1] = v.y; dst[2] = v.z; dst[3] = v.w;
        }
        __syncthreads();

        float c[8][4];
#pragma unroll
        for (int nl = 0; nl < 8; ++nl)
#pragma unroll
            for (int j = 0; j < 4; ++j) c[nl][j] = 0.0f;

        const int abase = (rt * 16 + g4) * 132;
#pragma unroll 4
        for (int ks = 0; ks < 16; ++ks) {
            const int k0 = ks * 8;
            uint32_t a0 = __float_as_uint(sA[abase + k0 + tig]);
            uint32_t a1 = __float_as_uint(sA[abase + 8 * 132 + k0 + tig]);
            uint32_t a2 = __float_as_uint(sA[abase + k0 + 4 + tig]);
            uint32_t a3 = __float_as_uint(sA[abase + 8 * 132 + k0 + 4 + tig]);
#pragma unroll
            for (int nl = 0; nl < 8; ++nl) {
                int nt = ch * 8 + nl;
                float2 bf = *(const float2*)&sWf[((ks * 16 + nt) * 32 + lane) * 2];
                mma_tf32(c[nl][0], c[nl][1], c[nl][2], c[nl][3],
                         a0, a1, a2, a3,
                         __float_as_uint(bf.x), __float_as_uint(bf.y));
            }
        }

        const int rowa = rowbase + rt * 16 + g4;
        const int rowb = rowa + 8;
        const bool va = rowa < NN, vb = rowb < NN;
#pragma unroll
        for (int nl = 0; nl < 8; ++nl) {
            if (va) {
                tloc[nl][0] += tanh_fast(c[nl][0] + kbv[nl].x);
                tloc[nl][1] += tanh_fast(c[nl][1] + kbv[nl].y);
            }
            if (vb) {
                tloc[nl][0] += tanh_fast(c[nl][2] + kbv[nl].x);
                tloc[nl][1] += tanh_fast(c[nl][3] + kbv[nl].y);
            }
        }
    }

#pragma unroll
    for (int nl = 0; nl < 8; ++nl) {
        int col = (ch * 8 + nl) * 8 + tig * 2;
        atomicAdd(&scol[col], tloc[nl][0]);
        atomicAdd(&scol[col + 1], tloc[nl][1]);
    }
    __syncthreads();
    if (tid < 128) atomicAdd(&colsum[tid], scol[tid]);
}

// ---------------------------------------------------------------------------
// Per-node attention logits, warp per node
// ---------------------------------------------------------------------------
__global__ void node_attn_kernel(const float* __restrict__ h,
                                 const float* __restrict__ att_src,
                                 const float* __restrict__ att_dst,
                                 float* __restrict__ asrc,
                                 float* __restrict__ adst, int n) {
    int gid = blockIdx.x * blockDim.x + threadIdx.x;
    int node = gid >> 5;
    int lane = gid & 31;
    if (node >= n) return;
    const float* hrow = h + (size_t)node * CC;
    float h00 = hrow[lane];
    float h01 = hrow[lane + 32];
    float h10 = hrow[lane + 64];
    float h11 = hrow[lane + 96];

    float r[8];
#pragma unroll
    for (int t = 0; t < MT; ++t) {
        const float* as = att_src + t * CC;
        const float* ad = att_dst + t * CC;
        r[t * 4 + 0] = h00 * as[lane] + h01 * as[lane + 32];
        r[t * 4 + 1] = h10 * as[lane + 64] + h11 * as[lane + 96];
        r[t * 4 + 2] = h00 * ad[lane] + h01 * ad[lane + 32];
        r[t * 4 + 3] = h10 * ad[lane + 64] + h11 * ad[lane + 96];
    }
#pragma unroll
    for (int i = 0; i < 8; ++i) {
#pragma unroll
        for (int off = 16; off > 0; off >>= 1)
            r[i] += __shfl_xor_sync(0xffffffffu, r[i], off);
    }
    if (lane == 0) {
#pragma unroll
        for (int t = 0; t < MT; ++t) {
            asrc[t * (NN * HH) + node * HH + 0] = r[t * 4 + 0];
            asrc[t * (NN * HH) + node * HH + 1] = r[t * 4 + 1];
            adst[t * (NN * HH) + node * HH + 0] = r[t * 4 + 2];
            adst[t * (NN * HH) + node * HH + 1] = r[t * 4 + 3];
        }
    }
}

// ---------------------------------------------------------------------------
// Edge softmax (measured path): alpha = exp(leaky(...)); asum[dst] += alpha
// ---------------------------------------------------------------------------
__global__ void edge_softmax_kernel(const int* __restrict__ ei,
                                    const float* __restrict__ asrc,
                                    const float* __restrict__ adst,
                                    float* __restrict__ alpha,
                                    float* __restrict__ asum) {
    int e = blockIdx.x * blockDim.x + threadIdx.x;
    if (e >= EE) return;
    int src = ei[e];
    int dst = ei[EE + e];
    float2 s = *(const float2*)&asrc[src * HH];
    float2 d = *(const float2*)&adst[dst * HH];
    float a0 = s.x + d.x;
    float a1 = s.y + d.y;
    float l0 = (a0 > 0.0f) ? a0 : 0.2f * a0;
    float l1 = (a1 > 0.0f) ? a1 : 0.2f * a1;
    float ex0 = expf(l0);
    float ex1 = expf(l1);
    *(float2*)&alpha[(size_t)e * HH] = make_float2(ex0, ex1);
    red_add_v2(&asum[dst * HH], ex0, ex1);
}

// ---------------------------------------------------------------------------
// Edge message (measured path): out[dst] += h[src]*coef  (32 lanes/edge)
// ---------------------------------------------------------------------------
__global__ void edge_message_kernel(const int* __restrict__ ei,
                                    const float* __restrict__ expalpha,
                                    const float* __restrict__ asum,
                                    const float* __restrict__ h,
                                    float* __restrict__ outT) {
    int gid = blockIdx.x * blockDim.x + threadIdx.x;
    int e = gid >> 5;
    int lane = gid & 31;
    if (e >= EE) return;
    int src = ei[e];
    int dst = ei[EE + e];
    int head = lane >> 4;
    float coef = expalpha[(size_t)e * HH + head] /
                 (asum[dst * HH + head] + 1e-16f);
    const float4* hrow = reinterpret_cast<const float4*>(h + (size_t)src * CC);
    float4 v = hrow[lane];
    float* o = outT + (size_t)dst * CC + lane * 4;
    red_add_v4(o, v.x * coef, v.y * coef, v.z * coef, v.w * coef);
}

// ---------------------------------------------------------------------------
// Semantic score + softmax (single block, 128 threads)
// ---------------------------------------------------------------------------
__global__ void score_softmax_kernel(const float* __restrict__ q,
                                     const float* __restrict__ colsum,
                                     float* __restrict__ attn) {
    __shared__ float red[128];
    int c = threadIdx.x;
    float s[MT];
#pragma unroll
    for (int m = 0; m < MT; ++m) {
        red[c] = q[c] * colsum[m * CC + c];
        __syncthreads();
        for (int off = 64; off > 0; off >>= 1) {
            if (c < off) red[c] += red[c + off];
            __syncthreads();
        }
        s[m] = red[0] * (1.0f / (float)NN);
        __syncthreads();
    }
    if (c == 0) {
        float mx = fmaxf(s[0], s[1]);
        float e0 = expf(s[0] - mx), e1 = expf(s[1] - mx);
        float inv = 1.0f / (e0 + e1);
        attn[0] = e0 * inv;
        attn[1] = e1 * inv;
    }
}

// ---------------------------------------------------------------------------
// Final linear fused with combine: warp per node
// ---------------------------------------------------------------------------
__global__ void final_linear_kernel(const float* __restrict__ o0,
                                    const float* __restrict__ o1,
                                    const float* __restrict__ attn,
                                    const float* __restrict__ lw,
                                    const float* __restrict__ lb,
                                    float* __restrict__ out) {
    int gid = blockIdx.x * blockDim.x + threadIdx.x;
    int node = gid >> 5;
    int lane = gid & 31;
    if (node >= NN) return;
    float a0 = attn[0], a1 = attn[1];
    float4 u = ((const float4*)(o0 + (size_t)node * CC))[lane];
    float4 v = ((const float4*)(o1 + (size_t)node * CC))[lane];
    float c0 = a0 * fmaxf(u.x, 0.f) + a1 * fmaxf(v.x, 0.f);
    float c1 = a0 * fmaxf(u.y, 0.f) + a1 * fmaxf(v.y, 0.f);
    float c2 = a0 * fmaxf(u.z, 0.f) + a1 * fmaxf(v.z, 0.f);
    float c3 = a0 * fmaxf(u.w, 0.f) + a1 * fmaxf(v.w, 0.f);
    const float* w = lw + lane * 4 * OUTD;
#pragma unroll
    for (int o = 0; o < OUTD; ++o) {
        float p = c0 * w[o] + c1 * w[OUTD + o] + c2 * w[2 * OUTD + o]
                + c3 * w[3 * OUTD + o];
#pragma unroll
        for (int off = 16; off > 0; off >>= 1)
            p += __shfl_xor_sync(0xffffffffu, p, off);
        if (lane == 0) out[(size_t)node * OUTD + o] = p + lb[o];
    }
}

// ---------------------------------------------------------------------------
// Host side
// ---------------------------------------------------------------------------
struct Scratch {
    float* h; float* out0; float* out1;
    float* asrc; float* adst; float* alpha;
    float* asum; float* colsum; float* attn;
};

#define GEMM_BLOCKS 296
#define SEM_SMEM ((16384 + 64 * 132) * sizeof(float))

static void run_han_layer(const float* input, const float* input2, int Kin,
                          const float* pw, const float* pb,
                          const float* att_src, const float* att_dst,
                          const float* q, const float* kw, const float* kb,
                          const int* ei0, const int* ei1, const Scratch& S) {
    if (Kin == 64) {
        size_t sm = (64 * 128 + 32 * 64) * sizeof(float);
        gemm_proj_kernel<64, false><<<GEMM_BLOCKS, 256, sm>>>(
            input, nullptr, nullptr, pw, pb, S.h);
    } else {
        size_t sm = (128 * 128 + 32 * 128) * sizeof(float);
        gemm_proj_kernel<128, true><<<GEMM_BLOCKS, 256, sm>>>(
            input, input2, S.attn, pw, pb, S.h);
    }

    node_attn_kernel<<<(NN * 32 + 255) / 256, 256>>>(S.h, att_src, att_dst,
                                                     S.asrc, S.adst, NN);

    cudaMemsetAsync(S.colsum, 0, MT * CC * sizeof(float));

    const int* eis[2] = {ei0, ei1};
    float* outs[2] = {S.out0, S.out1};
    for (int t = 0; t < MT; ++t) {
        cudaMemsetAsync(S.asum, 0, NN * HH * sizeof(float));
        cudaMemsetAsync(outs[t], 0, (size_t)NN * CC * sizeof(float));

        const float* asrc_t = S.asrc + t * (NN * HH);
        const float* adst_t = S.adst + t * (NN * HH);

        edge_softmax_kernel<<<(EE + 255) / 256, 256>>>(eis[t], asrc_t, adst_t,
                                                       S.alpha, S.asum);
        edge_message_kernel<<<(EE * 32 + 255) / 256, 256>>>(eis[t], S.alpha,
                                                            S.asum, S.h, outs[t]);
        semantic_tf32_kernel<<<GEMM_BLOCKS, 256, SEM_SMEM>>>(
            outs[t], kw, kb, S.colsum + t * CC);
    }

    score_softmax_kernel<<<1, 128>>>(q, S.colsum, S.attn);
}

extern "C" void kernel_launch(void* const* d_in, const int* in_sizes, int n_in,
                              void* d_out, int out_size) {
    const float *x = nullptr, *p1w = nullptr;
    const float *b128[6] = {nullptr};
    const float *a256[4] = {nullptr};
    const float *w16384[3] = {nullptr};
    const float *lin_w = nullptr, *lin_b = nullptr;
    const int *ei[2] = {nullptr, nullptr};
    int n128 = 0, n256 = 0, n16384 = 0, nei = 0;

    for (int i = 0; i < n_in; ++i) {
        int sz = in_sizes[i];
        const void* p = d_in[i];
        switch (sz) {
            case NN * FIN:      x = (const float*)p; break;
            case 2 * EE:        if (nei < 2) ei[nei++] = (const int*)p; break;
            case FIN * CC:      p1w = (const float*)p; break;
            case CC * CC:       if (n16384 < 3) w16384[n16384++] = (const float*)p; break;
            case MT * HH * DD:  if (n256 < 4) a256[n256++] = (const float*)p; break;
            case CC:            if (n128 < 6) b128[n128++] = (const float*)p; break;
            case CC * OUTD:     lin_w = (const float*)p; break;
            case OUTD:          lin_b = (const float*)p; break;
            default: break;
        }
    }
    const float* p1_kw = w16384[0];
    const float* p2w   = w16384[1];
    const float* p2_kw = w16384[2];
    const float *p1_pb = b128[0], *p1_q = b128[1], *p1_kb = b128[2];
    const float *p2_pb = b128[3], *p2_q = b128[4], *p2_kb = b128[5];
    const float *p1_as = a256[0], *p1_ad = a256[1];
    const float *p2_as = a256[2], *p2_ad = a256[3];

    (void)cudaFuncSetAttribute(gemm_proj_kernel<64, false>,
                               cudaFuncAttributeMaxDynamicSharedMemorySize, 100 * 1024);
    (void)cudaFuncSetAttribute(gemm_proj_kernel<128, true>,
                               cudaFuncAttributeMaxDynamicSharedMemorySize, 100 * 1024);
    (void)cudaFuncSetAttribute(semantic_tf32_kernel,
                               cudaFuncAttributeMaxDynamicSharedMemorySize, 100 * 1024);

    Scratch S;
    cudaGetSymbolAddress((void**)&S.h, g_h);
    cudaGetSymbolAddress((void**)&S.out0, g_out0);
    cudaGetSymbolAddress((void**)&S.out1, g_out1);
    cudaGetSymbolAddress((void**)&S.asrc, g_asrc);
    cudaGetSymbolAddress((void**)&S.adst, g_adst);
    cudaGetSymbolAddress((void**)&S.alpha, g_alpha);
    cudaGetSymbolAddress((void**)&S.asum, g_asum);
    cudaGetSymbolAddress((void**)&S.colsum, g_colsum);
    cudaGetSymbolAddress((void**)&S.attn, g_attn);

    // Layer 1: IN=64 -> C=128
    run_han_layer(x, nullptr, 64, p1w, p1_pb, p1_as, p1_ad, p1_q, p1_kw, p1_kb,
                  ei[0], ei[1], S);
    // Layer 2: combine fused into projection A-load
    run_han_layer(S.out0, S.out1, 128, p2w, p2_pb, p2_as, p2_ad, p2_q, p2_kw,
                  p2_kb, ei[0], ei[1], S);

    // Final classifier (combine fused)
    final_linear_kernel<<<(NN * 32 + 255) / 256, 256>>>(
        S.out0, S.out1, S.attn, lin_w, lin_b, (float*)d_out);
}

// round 11
// speedup vs baseline: 1.7744x; 1.1440x over previous
#include <cuda_runtime.h>
#include <math.h>
#include <stdint.h>

// Problem constants
#define NN   100000
#define FIN  64
#define CC   128
#define HH   2
#define DD   64
#define EE   600000
#define MT   2
#define OUTD 8

// ---------------------------------------------------------------------------
// Scratch (device globals — no allocation allowed)
// ---------------------------------------------------------------------------
__device__ float    g_h[(size_t)NN * CC];
__device__ float    g_out0[(size_t)NN * CC];
__device__ float    g_out1[(size_t)NN * CC];
__device__ float    g_asrc[MT * NN * HH];
__device__ float    g_adst[MT * NN * HH];
__device__ float    g_alpha[(size_t)EE * HH];
__device__ float    g_asum[NN * HH];
__device__ float    g_colsum[MT * CC];
__device__ float    g_attn[MT];

// ---------------------------------------------------------------------------
// Helpers
// ---------------------------------------------------------------------------
__device__ __forceinline__ uint64_t splat2(float x) {
    uint64_t r;
    asm("mov.b64 %0, {%1, %1};" : "=l"(r) : "f"(x));
    return r;
}
__device__ __forceinline__ void fma2(uint64_t& acc, uint64_t a, uint64_t b) {
    asm("fma.rn.f32x2 %0, %1, %2, %0;" : "+l"(acc) : "l"(a), "l"(b));
}
__device__ __forceinline__ float2 unpack2(uint64_t v) {
    float2 f;
    asm("mov.b64 {%0, %1}, %2;" : "=f"(f.x), "=f"(f.y) : "l"(v));
    return f;
}
__device__ __forceinline__ float tanh_fast(float x) {
    float y;
    asm("tanh.approx.f32 %0, %1;" : "=f"(y) : "f"(x));
    return y;
}
__device__ __forceinline__ void red_add_v4(float* p, float x, float y, float z, float w) {
    asm volatile("red.global.add.v4.f32 [%0], {%1,%2,%3,%4};"
                 :: "l"(p), "f"(x), "f"(y), "f"(z), "f"(w) : "memory");
}
__device__ __forceinline__ void red_add_v2(float* p, float x, float y) {
    asm volatile("red.global.add.v2.f32 [%0], {%1,%2};"
                 :: "l"(p), "f"(x), "f"(y) : "memory");
}
__device__ __forceinline__ float f2tf32f(float f) {
    uint32_t u;
    asm("cvt.rna.tf32.f32 %0, %1;" : "=r"(u) : "f"(f));
    return __uint_as_float(u);
}
__device__ __forceinline__ void mma_tf32(float& c0, float& c1, float& c2, float& c3,
                                         uint32_t a0, uint32_t a1, uint32_t a2, uint32_t a3,
                                         uint32_t b0, uint32_t b1) {
    asm volatile(
        "mma.sync.aligned.m16n8k8.row.col.f32.tf32.tf32.f32 "
        "{%0,%1,%2,%3}, {%4,%5,%6,%7}, {%8,%9}, {%0,%1,%2,%3};"
        : "+f"(c0), "+f"(c1), "+f"(c2), "+f"(c3)
        : "r"(a0), "r"(a1), "r"(a2), "r"(a3), "r"(b0), "r"(b1));
}

// ---------------------------------------------------------------------------
// Projection GEMM (R2/R4 measured shape): out = A @ W + b
// 32-row tiles, 4x4 per-thread, persistent, W smem-resident, f32x2 FMA.
// FUSED (layer-2): A row := attn0*relu(o0) + attn1*relu(o1)
// ---------------------------------------------------------------------------
template <int K, bool FUSED>
__global__ void gemm_proj_kernel(const float* __restrict__ A,
                                 const float* __restrict__ A2,
                                 const float* __restrict__ attn,
                                 const float* __restrict__ W,
                                 const float* __restrict__ b,
                                 float* __restrict__ out) {
    extern __shared__ float smem[];
    float* sW = smem;             // [K][128]
    float* sA = smem + K * 128;   // [32][K]
    const int tid = threadIdx.x;
    const int cg = tid & 31;
    const int rg = tid >> 5;

    for (int idx = tid; idx < K * 128; idx += 256) sW[idx] = W[idx];
    float4 b4 = *(const float4*)&b[cg * 4];
    float at0 = 0.f, at1 = 0.f;
    if (FUSED) { at0 = attn[0]; at1 = attn[1]; }

    const int ntiles = NN / 32;   // NN % 32 == 0
    for (int tile = blockIdx.x; tile < ntiles; tile += gridDim.x) {
        __syncthreads();
        const float4* Ab  = (const float4*)(A  + (size_t)tile * 32 * K);
        const float4* Ab2 = FUSED ? (const float4*)(A2 + (size_t)tile * 32 * K)
                                  : nullptr;
        for (int idx = tid; idx < 32 * (K / 4); idx += 256) {
            float4 v;
            if (FUSED) {
                float4 u = Ab[idx], w = Ab2[idx];
                v.x = at0 * fmaxf(u.x, 0.f) + at1 * fmaxf(w.x, 0.f);
                v.y = at0 * fmaxf(u.y, 0.f) + at1 * fmaxf(w.y, 0.f);
                v.z = at0 * fmaxf(u.z, 0.f) + at1 * fmaxf(w.z, 0.f);
                v.w = at0 * fmaxf(u.w, 0.f) + at1 * fmaxf(w.w, 0.f);
            } else {
                v = Ab[idx];
            }
            ((float4*)sA)[idx] = v;
        }
        __syncthreads();

        uint64_t acc[4][2];
#pragma unroll
        for (int r = 0; r < 4; ++r) { acc[r][0] = 0ull; acc[r][1] = 0ull; }

#pragma unroll 2
        for (int k4 = 0; k4 < K; k4 += 4) {
            float4 a[4];
#pragma unroll
            for (int r = 0; r < 4; ++r)
                a[r] = *(const float4*)&sA[(4 * rg + r) * K + k4];
#pragma unroll
            for (int kk = 0; kk < 4; ++kk) {
                ulonglong2 wv = *(const ulonglong2*)&sW[(k4 + kk) * 128 + cg * 4];
#pragma unroll
                for (int r = 0; r < 4; ++r) {
                    float av = (kk == 0) ? a[r].x : (kk == 1) ? a[r].y
                             : (kk == 2) ? a[r].z : a[r].w;
                    uint64_t a2 = splat2(av);
                    fma2(acc[r][0], a2, wv.x);
                    fma2(acc[r][1], a2, wv.y);
                }
            }
        }
#pragma unroll
        for (int r = 0; r < 4; ++r) {
            float2 p0 = unpack2(acc[r][0]);
            float2 p1 = unpack2(acc[r][1]);
            float4 o = make_float4(p0.x + b4.x, p0.y + b4.y, p1.x + b4.z, p1.y + b4.w);
            int row = tile * 32 + 4 * rg + r;
            *(float4*)&out[(size_t)row * 128 + cg * 4] = o;
        }
    }
}

// ---------------------------------------------------------------------------
// Semantic GEMM, tf32 tensor cores with fragment-major W staging (R10 WIN).
// colsum[c] += sum_n tanh( relu(A[n,:]) @ kw[:,c] + kb[c] )
// ---------------------------------------------------------------------------
#define SEM_TILES ((NN + 63) / 64)
__global__ void __launch_bounds__(256)
semantic_tf32_kernel(const float* __restrict__ A,
                     const float* __restrict__ kw,
                     const float* __restrict__ kb,
                     float* __restrict__ colsum) {
    extern __shared__ float smem[];
    float* sWf = smem;            // 16384 floats
    float* sA  = smem + 16384;    // [64][132] = 8448 floats
    __shared__ float scol[128];
    const int tid  = threadIdx.x;
    const int lane = tid & 31;
    const int warp = tid >> 5;
    const int g4   = lane >> 2;
    const int tig  = lane & 3;
    const int rt   = warp & 3;
    const int ch   = warp >> 2;

    for (int i4 = tid; i4 < 4096; i4 += 256) {
        int k  = i4 >> 5;
        int n0 = (i4 & 31) * 4;
        float4 w4 = ((const float4*)kw)[i4];
        float wv[4] = {w4.x, w4.y, w4.z, w4.w};
        int ks = k >> 3;
        int slot = (k & 7) >> 2;
        int km = k & 3;
#pragma unroll
        for (int j = 0; j < 4; ++j) {
            int n = n0 + j;
            int nt = n >> 3;
            int ln = (n & 7) * 4 + km;
            sWf[(((ks * 16) + nt) * 32 + ln) * 2 + slot] = f2tf32f(wv[j]);
        }
    }
    if (tid < 128) scol[tid] = 0.0f;

    float2 kbv[8];
#pragma unroll
    for (int nl = 0; nl < 8; ++nl)
        kbv[nl] = *(const float2*)&kb[(ch * 8 + nl) * 8 + tig * 2];

    float tloc[8][2];
#pragma unroll
    for (int nl = 0; nl < 8; ++nl) { tloc[nl][0] = 0.f; tloc[nl][1] = 0.f; }

    for (int tile = blockIdx.x; tile < SEM_TILES; tile += gridDim.x) {
        __syncthreads();
        const int rowbase = tile * 64;
        const float4* Ab = (const float4*)(A + (size_t)rowbase * 128);
        for (int i4 = tid; i4 < 2048; i4 += 256) {
            int r = i4 >> 5, k4 = i4 & 31;
            float4 v = make_float4(0.f, 0.f, 0.f, 0.f);
            if (rowbase + r < NN) {
                float4 u = Ab[i4];
                v.x = f2tf32f(fmaxf(u.x, 0.f));
                v.y = f2tf32f(fmaxf(u.y, 0.f));
                v.z = f2tf32f(fmaxf(u.z, 0.f));
                v.w = f2tf32f(fmaxf(u.w, 0.f));
            }
            float* dst = &sA[r * 132 + k4 * 4];
            dst[0] = v.x; dst[1] = v.y; dst[2] = v.z; dst[3] = v.w;
        }
        __syncthreads();

        float c[8][4];
#pragma unroll
        for (int nl = 0; nl < 8; ++nl)
#pragma unroll
            for (int j = 0; j < 4; ++j) c[nl][j] = 0.0f;

        const int abase = (rt * 16 + g4) * 132;
#pragma unroll 4
        for (int ks = 0; ks < 16; ++ks) {
            const int k0 = ks * 8;
            uint32_t a0 = __float_as_uint(sA[abase + k0 + tig]);
            uint32_t a1 = __float_as_uint(sA[abase + 8 * 132 + k0 + tig]);
            uint32_t a2 = __float_as_uint(sA[abase + k0 + 4 + tig]);
            uint32_t a3 = __float_as_uint(sA[abase + 8 * 132 + k0 + 4 + tig]);
#pragma unroll
            for (int nl = 0; nl < 8; ++nl) {
                int nt = ch * 8 + nl;
                float2 bf = *(const float2*)&sWf[((ks * 16 + nt) * 32 + lane) * 2];
                mma_tf32(c[nl][0], c[nl][1], c[nl][2], c[nl][3],
                         a0, a1, a2, a3,
                         __float_as_uint(bf.x), __float_as_uint(bf.y));
            }
        }

        const int rowa = rowbase + rt * 16 + g4;
        const int rowb = rowa + 8;
        const bool va = rowa < NN, vb = rowb < NN;
#pragma unroll
        for (int nl = 0; nl < 8; ++nl) {
            if (va) {
                tloc[nl][0] += tanh_fast(c[nl][0] + kbv[nl].x);
                tloc[nl][1] += tanh_fast(c[nl][1] + kbv[nl].y);
            }
            if (vb) {
                tloc[nl][0] += tanh_fast(c[nl][2] + kbv[nl].x);
                tloc[nl][1] += tanh_fast(c[nl][3] + kbv[nl].y);
            }
        }
    }

#pragma unroll
    for (int nl = 0; nl < 8; ++nl) {
        int col = (ch * 8 + nl) * 8 + tig * 2;
        atomicAdd(&scol[col], tloc[nl][0]);
        atomicAdd(&scol[col + 1], tloc[nl][1]);
    }
    __syncthreads();
    if (tid < 128) atomicAdd(&colsum[tid], scol[tid]);
}

// ---------------------------------------------------------------------------
// Per-node attention logits, warp per node
// ---------------------------------------------------------------------------
__global__ void node_attn_kernel(const float* __restrict__ h,
                                 const float* __restrict__ att_src,
                                 const float* __restrict__ att_dst,
                                 float* __restrict__ asrc,
                                 float* __restrict__ adst, int n) {
    int gid = blockIdx.x * blockDim.x + threadIdx.x;
    int node = gid >> 5;
    int lane = gid & 31;
    if (node >= n) return;
    const float* hrow = h + (size_t)node * CC;
    float h00 = hrow[lane];
    float h01 = hrow[lane + 32];
    float h10 = hrow[lane + 64];
    float h11 = hrow[lane + 96];

    float r[8];
#pragma unroll
    for (int t = 0; t < MT; ++t) {
        const float* as = att_src + t * CC;
        const float* ad = att_dst + t * CC;
        r[t * 4 + 0] = h00 * as[lane] + h01 * as[lane + 32];
        r[t * 4 + 1] = h10 * as[lane + 64] + h11 * as[lane + 96];
        r[t * 4 + 2] = h00 * ad[lane] + h01 * ad[lane + 32];
        r[t * 4 + 3] = h10 * ad[lane + 64] + h11 * ad[lane + 96];
    }
#pragma unroll
    for (int i = 0; i < 8; ++i) {
#pragma unroll
        for (int off = 16; off > 0; off >>= 1)
            r[i] += __shfl_xor_sync(0xffffffffu, r[i], off);
    }
    if (lane == 0) {
#pragma unroll
        for (int t = 0; t < MT; ++t) {
            asrc[t * (NN * HH) + node * HH + 0] = r[t * 4 + 0];
            asrc[t * (NN * HH) + node * HH + 1] = r[t * 4 + 1];
            adst[t * (NN * HH) + node * HH + 0] = r[t * 4 + 2];
            adst[t * (NN * HH) + node * HH + 1] = r[t * 4 + 3];
        }
    }
}

// ---------------------------------------------------------------------------
// Edge softmax (measured path): alpha = exp(leaky(...)); asum[dst] += alpha
// ---------------------------------------------------------------------------
__global__ void edge_softmax_kernel(const int* __restrict__ ei,
                                    const float* __restrict__ asrc,
                                    const float* __restrict__ adst,
                                    float* __restrict__ alpha,
                                    float* __restrict__ asum) {
    int e = blockIdx.x * blockDim.x + threadIdx.x;
    if (e >= EE) return;
    int src = ei[e];
    int dst = ei[EE + e];
    float2 s = *(const float2*)&asrc[src * HH];
    float2 d = *(const float2*)&adst[dst * HH];
    float a0 = s.x + d.x;
    float a1 = s.y + d.y;
    float l0 = (a0 > 0.0f) ? a0 : 0.2f * a0;
    float l1 = (a1 > 0.0f) ? a1 : 0.2f * a1;
    float ex0 = expf(l0);
    float ex1 = expf(l1);
    *(float2*)&alpha[(size_t)e * HH] = make_float2(ex0, ex1);
    red_add_v2(&asum[dst * HH], ex0, ex1);
}

// ---------------------------------------------------------------------------
// Edge message, 4 edges per warp (MLP batching):
// one int4 load -> 4 srcs, one int4 -> 4 dsts; 4 alpha + 4 asum + 4 h-row
// loads all independent -> ~12-deep MLP instead of the serial 1-edge chain.
// out[dst_i] += h[src_i] * coef_i via red.v4.  EE % 4 == 0.
// ---------------------------------------------------------------------------
__global__ void edge_message_kernel(const int* __restrict__ ei,
                                    const float* __restrict__ expalpha,
                                    const float* __restrict__ asum,
                                    const float* __restrict__ h,
                                    float* __restrict__ outT) {
    int gid = blockIdx.x * blockDim.x + threadIdx.x;
    int w = gid >> 5;               // warp id = group of 4 edges
    int lane = gid & 31;
    if (w >= EE / 4) return;
    const int e0 = w * 4;
    const int head = lane >> 4;

    int4 s4 = ((const int4*)ei)[w];            // src[e0..e0+3]
    int4 d4 = ((const int4*)ei)[EE / 4 + w];   // dst[e0..e0+3]
    int srcs[4] = {s4.x, s4.y, s4.z, s4.w};
    int dsts[4] = {d4.x, d4.y, d4.z, d4.w};

    // Independent loads — alpha (one 32B sector), asum (4 broadcasts)
    float av[4], sv[4];
#pragma unroll
    for (int i = 0; i < 4; ++i)
        av[i] = expalpha[(size_t)(e0 + i) * HH + head];
#pragma unroll
    for (int i = 0; i < 4; ++i)
        sv[i] = asum[dsts[i] * HH + head];

    // 4 independent 512B row gathers
    float4 v[4];
#pragma unroll
    for (int i = 0; i < 4; ++i)
        v[i] = ((const float4*)(h + (size_t)srcs[i] * CC))[lane];

#pragma unroll
    for (int i = 0; i < 4; ++i) {
        float coef = av[i] / (sv[i] + 1e-16f);
        float* o = outT + (size_t)dsts[i] * CC + lane * 4;
        red_add_v4(o, v[i].x * coef, v[i].y * coef, v[i].z * coef, v[i].w * coef);
    }
}

// ---------------------------------------------------------------------------
// Semantic score + softmax (single block, 128 threads)
// ---------------------------------------------------------------------------
__global__ void score_softmax_kernel(const float* __restrict__ q,
                                     const float* __restrict__ colsum,
                                     float* __restrict__ attn) {
    __shared__ float red[128];
    int c = threadIdx.x;
    float s[MT];
#pragma unroll
    for (int m = 0; m < MT; ++m) {
        red[c] = q[c] * colsum[m * CC + c];
        __syncthreads();
        for (int off = 64; off > 0; off >>= 1) {
            if (c < off) red[c] += red[c + off];
            __syncthreads();
        }
        s[m] = red[0] * (1.0f / (float)NN);
        __syncthreads();
    }
    if (c == 0) {
        float mx = fmaxf(s[0], s[1]);
        float e0 = expf(s[0] - mx), e1 = expf(s[1] - mx);
        float inv = 1.0f / (e0 + e1);
        attn[0] = e0 * inv;
        attn[1] = e1 * inv;
    }
}

// ---------------------------------------------------------------------------
// Final linear fused with combine: warp per node
// ---------------------------------------------------------------------------
__global__ void final_linear_kernel(const float* __restrict__ o0,
                                    const float* __restrict__ o1,
                                    const float* __restrict__ attn,
                                    const float* __restrict__ lw,
                                    const float* __restrict__ lb,
                                    float* __restrict__ out) {
    int gid = blockIdx.x * blockDim.x + threadIdx.x;
    int node = gid >> 5;
    int lane = gid & 31;
    if (node >= NN) return;
    float a0 = attn[0], a1 = attn[1];
    float4 u = ((const float4*)(o0 + (size_t)node * CC))[lane];
    float4 v = ((const float4*)(o1 + (size_t)node * CC))[lane];
    float c0 = a0 * fmaxf(u.x, 0.f) + a1 * fmaxf(v.x, 0.f);
    float c1 = a0 * fmaxf(u.y, 0.f) + a1 * fmaxf(v.y, 0.f);
    float c2 = a0 * fmaxf(u.z, 0.f) + a1 * fmaxf(v.z, 0.f);
    float c3 = a0 * fmaxf(u.w, 0.f) + a1 * fmaxf(v.w, 0.f);
    const float* w = lw + lane * 4 * OUTD;
#pragma unroll
    for (int o = 0; o < OUTD; ++o) {
        float p = c0 * w[o] + c1 * w[OUTD + o] + c2 * w[2 * OUTD + o]
                + c3 * w[3 * OUTD + o];
#pragma unroll
        for (int off = 16; off > 0; off >>= 1)
            p += __shfl_xor_sync(0xffffffffu, p, off);
        if (lane == 0) out[(size_t)node * OUTD + o] = p + lb[o];
    }
}

// ---------------------------------------------------------------------------
// Host side
// ---------------------------------------------------------------------------
struct Scratch {
    float* h; float* out0; float* out1;
    float* asrc; float* adst; float* alpha;
    float* asum; float* colsum; float* attn;
};

#define GEMM_BLOCKS 296
#define SEM_SMEM ((16384 + 64 * 132) * sizeof(float))

static void run_han_layer(const float* input, const float* input2, int Kin,
                          const float* pw, const float* pb,
                          const float* att_src, const float* att_dst,
                          const float* q, const float* kw, const float* kb,
                          const int* ei0, const int* ei1, const Scratch& S) {
    if (Kin == 64) {
        size_t sm = (64 * 128 + 32 * 64) * sizeof(float);
        gemm_proj_kernel<64, false><<<GEMM_BLOCKS, 256, sm>>>(
            input, nullptr, nullptr, pw, pb, S.h);
    } else {
        size_t sm = (128 * 128 + 32 * 128) * sizeof(float);
        gemm_proj_kernel<128, true><<<GEMM_BLOCKS, 256, sm>>>(
            input, input2, S.attn, pw, pb, S.h);
    }

    node_attn_kernel<<<(NN * 32 + 255) / 256, 256>>>(S.h, att_src, att_dst,
                                                     S.asrc, S.adst, NN);

    cudaMemsetAsync(S.colsum, 0, MT * CC * sizeof(float));

    const int* eis[2] = {ei0, ei1};
    float* outs[2] = {S.out0, S.out1};
    for (int t = 0; t < MT; ++t) {
        cudaMemsetAsync(S.asum, 0, NN * HH * sizeof(float));
        cudaMemsetAsync(outs[t], 0, (size_t)NN * CC * sizeof(float));

        const float* asrc_t = S.asrc + t * (NN * HH);
        const float* adst_t = S.adst + t * (NN * HH);

        edge_softmax_kernel<<<(EE + 255) / 256, 256>>>(eis[t], asrc_t, adst_t,
                                                       S.alpha, S.asum);
        edge_message_kernel<<<(EE * 8 + 255) / 256, 256>>>(eis[t], S.alpha,
                                                           S.asum, S.h, outs[t]);
        semantic_tf32_kernel<<<GEMM_BLOCKS, 256, SEM_SMEM>>>(
            outs[t], kw, kb, S.colsum + t * CC);
    }

    score_softmax_kernel<<<1, 128>>>(q, S.colsum, S.attn);
}

extern "C" void kernel_launch(void* const* d_in, const int* in_sizes, int n_in,
                              void* d_out, int out_size) {
    const float *x = nullptr, *p1w = nullptr;
    const float *b128[6] = {nullptr};
    const float *a256[4] = {nullptr};
    const float *w16384[3] = {nullptr};
    const float *lin_w = nullptr, *lin_b = nullptr;
    const int *ei[2] = {nullptr, nullptr};
    int n128 = 0, n256 = 0, n16384 = 0, nei = 0;

    for (int i = 0; i < n_in; ++i) {
        int sz = in_sizes[i];
        const void* p = d_in[i];
        switch (sz) {
            case NN * FIN:      x = (const float*)p; break;
            case 2 * EE:        if (nei < 2) ei[nei++] = (const int*)p; break;
            case FIN * CC:      p1w = (const float*)p; break;
            case CC * CC:       if (n16384 < 3) w16384[n16384++] = (const float*)p; break;
            case MT * HH * DD:  if (n256 < 4) a256[n256++] = (const float*)p; break;
            case CC:            if (n128 < 6) b128[n128++] = (const float*)p; break;
            case CC * OUTD:     lin_w = (const float*)p; break;
            case OUTD:          lin_b = (const float*)p; break;
            default: break;
        }
    }
    const float* p1_kw = w16384[0];
    const float* p2w   = w16384[1];
    const float* p2_kw = w16384[2];
    const float *p1_pb = b128[0], *p1_q = b128[1], *p1_kb = b128[2];
    const float *p2_pb = b128[3], *p2_q = b128[4], *p2_kb = b128[5];
    const float *p1_as = a256[0], *p1_ad = a256[1];
    const float *p2_as = a256[2], *p2_ad = a256[3];

    (void)cudaFuncSetAttribute(gemm_proj_kernel<64, false>,
                               cudaFuncAttributeMaxDynamicSharedMemorySize, 100 * 1024);
    (void)cudaFuncSetAttribute(gemm_proj_kernel<128, true>,
                               cudaFuncAttributeMaxDynamicSharedMemorySize, 100 * 1024);
    (void)cudaFuncSetAttribute(semantic_tf32_kernel,
                               cudaFuncAttributeMaxDynamicSharedMemorySize, 100 * 1024);

    Scratch S;
    cudaGetSymbolAddress((void**)&S.h, g_h);
    cudaGetSymbolAddress((void**)&S.out0, g_out0);
    cudaGetSymbolAddress((void**)&S.out1, g_out1);
    cudaGetSymbolAddress((void**)&S.asrc, g_asrc);
    cudaGetSymbolAddress((void**)&S.adst, g_adst);
    cudaGetSymbolAddress((void**)&S.alpha, g_alpha);
    cudaGetSymbolAddress((void**)&S.asum, g_asum);
    cudaGetSymbolAddress((void**)&S.colsum, g_colsum);
    cudaGetSymbolAddress((void**)&S.attn, g_attn);

    // Layer 1: IN=64 -> C=128
    run_han_layer(x, nullptr, 64, p1w, p1_pb, p1_as, p1_ad, p1_q, p1_kw, p1_kb,
                  ei[0], ei[1], S);
    // Layer 2: combine fused into projection A-load
    run_han_layer(S.out0, S.out1, 128, p2w, p2_pb, p2_as, p2_ad, p2_q, p2_kw,
                  p2_kb, ei[0], ei[1], S);

    // Final classifier (combine fused)
    final_linear_kernel<<<(NN * 32 + 255) / 256, 256>>>(
        S.out0, S.out1, S.attn, lin_w, lin_b, (float*)d_out);
}

// round 14
// speedup vs baseline: 1.8544x; 1.0451x over previous
#include <cuda_runtime.h>
#include <math.h>
#include <stdint.h>

// Problem constants
#define NN   100000
#define FIN  64
#define CC   128
#define HH   2
#define DD   64
#define EE   600000
#define MT   2
#define OUTD 8

// ---------------------------------------------------------------------------
// Scratch (device globals — no allocation allowed)
// ---------------------------------------------------------------------------
__device__ float    g_h[(size_t)NN * CC];
__device__ float    g_out0[(size_t)NN * CC];
__device__ float    g_out1[(size_t)NN * CC];
__device__ float    g_asrc[MT * NN * HH];
__device__ float    g_adst[MT * NN * HH];
__device__ float    g_alpha[(size_t)EE * HH];
__device__ float    g_asum[NN * HH];
__device__ float    g_colsum[MT * CC];
__device__ float    g_attn[MT];

// ---------------------------------------------------------------------------
// Helpers
// ---------------------------------------------------------------------------
__device__ __forceinline__ float tanh_fast(float x) {
    float y;
    asm("tanh.approx.f32 %0, %1;" : "=f"(y) : "f"(x));
    return y;
}
__device__ __forceinline__ void red_add_v4(float* p, float x, float y, float z, float w) {
    asm volatile("red.global.add.v4.f32 [%0], {%1,%2,%3,%4};"
                 :: "l"(p), "f"(x), "f"(y), "f"(z), "f"(w) : "memory");
}
__device__ __forceinline__ void red_add_v2(float* p, float x, float y) {
    asm volatile("red.global.add.v2.f32 [%0], {%1,%2};"
                 :: "l"(p), "f"(x), "f"(y) : "memory");
}
__device__ __forceinline__ float f2tf32f(float f) {
    uint32_t u;
    asm("cvt.rna.tf32.f32 %0, %1;" : "=r"(u) : "f"(f));
    return __uint_as_float(u);
}
__device__ __forceinline__ void mma_tf32(float& c0, float& c1, float& c2, float& c3,
                                         uint32_t a0, uint32_t a1, uint32_t a2, uint32_t a3,
                                         uint32_t b0, uint32_t b1) {
    asm volatile(
        "mma.sync.aligned.m16n8k8.row.col.f32.tf32.tf32.f32 "
        "{%0,%1,%2,%3}, {%4,%5,%6,%7}, {%8,%9}, {%0,%1,%2,%3};"
        : "+f"(c0), "+f"(c1), "+f"(c2), "+f"(c3)
        : "r"(a0), "r"(a1), "r"(a2), "r"(a3), "r"(b0), "r"(b1));
}

// ===========================================================================
// tf32 GEMM core layout (validated in R10):
// 64-row x 128-col tile, K in {64,128}. 8 warps: rt=warp%4 (16-row tile),
// ch=warp/4 (column half, 8 n-tiles of 8 cols each).
// W staged ONCE per persistent block in m16n8k8 fragment order:
//   (k,n): kstep=k/8, nt=n/8, lane=(n%8)*4+(k%4), slot=(k%8)/4
// A staged row-major stride K+4, tf32-converted.
// Compute per kstep: 4 scalar A LDS + 1 float2 W LDS per MMA.
// ===========================================================================

// ---------------------------------------------------------------------------
// tf32 projection GEMM: out[n,c] = A[n,:K] @ W[K,128] + b[c]
// FUSED (layer-2): A row := attn0*relu(o0) + attn1*relu(o1)
// ---------------------------------------------------------------------------
template <int K, bool FUSED>
__global__ void __launch_bounds__(256)
proj_tf32_kernel(const float* __restrict__ A,
                 const float* __restrict__ A2,
                 const float* __restrict__ attn,
                 const float* __restrict__ W,
                 const float* __restrict__ b,
                 float* __restrict__ out) {
    extern __shared__ float smem[];
    float* sWf = smem;                // K*128 floats
    float* sA  = smem + K * 128;      // [64][K+4]
    const int tid  = threadIdx.x;
    const int lane = tid & 31;
    const int warp = tid >> 5;
    const int g4   = lane >> 2;
    const int tig  = lane & 3;
    const int rt   = warp & 3;
    const int ch   = warp >> 2;
    const int KS = K + 4;

    // Stage W fragments once
    for (int i4 = tid; i4 < K * 32; i4 += 256) {
        int k  = i4 >> 5;
        int n0 = (i4 & 31) * 4;
        float4 w4 = ((const float4*)W)[i4];
        float wv[4] = {w4.x, w4.y, w4.z, w4.w};
        int ks = k >> 3;
        int slot = (k & 7) >> 2;
        int km = k & 3;
#pragma unroll
        for (int j = 0; j < 4; ++j) {
            int n = n0 + j;
            int nt = n >> 3;
            int ln = (n & 7) * 4 + km;
            sWf[(((ks * 16) + nt) * 32 + ln) * 2 + slot] = f2tf32f(wv[j]);
        }
    }

    float2 bv[8];
#pragma unroll
    for (int nl = 0; nl < 8; ++nl)
        bv[nl] = *(const float2*)&b[(ch * 8 + nl) * 8 + tig * 2];

    float at0 = 0.f, at1 = 0.f;
    if (FUSED) { at0 = attn[0]; at1 = attn[1]; }

    const int ntiles = (NN + 63) / 64;
    for (int tile = blockIdx.x; tile < ntiles; tile += gridDim.x) {
        __syncthreads();
        const int rowbase = tile * 64;
        const float4* Ab  = (const float4*)(A  + (size_t)rowbase * K);
        const float4* Ab2 = FUSED ? (const float4*)(A2 + (size_t)rowbase * K)
                                  : nullptr;
        for (int i4 = tid; i4 < 64 * (K / 4); i4 += 256) {
            int r = i4 / (K / 4), k4 = i4 % (K / 4);
            float4 v = make_float4(0.f, 0.f, 0.f, 0.f);
            if (rowbase + r < NN) {
                if (FUSED) {
                    float4 u = Ab[i4], w = Ab2[i4];
                    v.x = f2tf32f(at0 * fmaxf(u.x, 0.f) + at1 * fmaxf(w.x, 0.f));
                    v.y = f2tf32f(at0 * fmaxf(u.y, 0.f) + at1 * fmaxf(w.y, 0.f));
                    v.z = f2tf32f(at0 * fmaxf(u.z, 0.f) + at1 * fmaxf(w.z, 0.f));
                    v.w = f2tf32f(at0 * fmaxf(u.w, 0.f) + at1 * fmaxf(w.w, 0.f));
                } else {
                    float4 u = Ab[i4];
                    v.x = f2tf32f(u.x); v.y = f2tf32f(u.y);
                    v.z = f2tf32f(u.z); v.w = f2tf32f(u.w);
                }
            }
            float* dst = &sA[r * KS + k4 * 4];
            dst[0] = v.x; dst[1] = v.y; dst[2] = v.z; dst[3] = v.w;
        }
        __syncthreads();

        float c[8][4];
#pragma unroll
        for (int nl = 0; nl < 8; ++nl)
#pragma unroll
            for (int j = 0; j < 4; ++j) c[nl][j] = 0.0f;

        const int abase = (rt * 16 + g4) * KS;
#pragma unroll 4
        for (int ks = 0; ks < K / 8; ++ks) {
            const int k0 = ks * 8;
            uint32_t a0 = __float_as_uint(sA[abase + k0 + tig]);
            uint32_t a1 = __float_as_uint(sA[abase + 8 * KS + k0 + tig]);
            uint32_t a2 = __float_as_uint(sA[abase + k0 + 4 + tig]);
            uint32_t a3 = __float_as_uint(sA[abase + 8 * KS + k0 + 4 + tig]);
#pragma unroll
            for (int nl = 0; nl < 8; ++nl) {
                int nt = ch * 8 + nl;
                float2 bf = *(const float2*)&sWf[((ks * 16 + nt) * 32 + lane) * 2];
                mma_tf32(c[nl][0], c[nl][1], c[nl][2], c[nl][3],
                         a0, a1, a2, a3,
                         __float_as_uint(bf.x), __float_as_uint(bf.y));
            }
        }

        const int rowa = rowbase + rt * 16 + g4;
        const int rowb = rowa + 8;
#pragma unroll
        for (int nl = 0; nl < 8; ++nl) {
            int col = (ch * 8 + nl) * 8 + tig * 2;
            if (rowa < NN)
                *(float2*)&out[(size_t)rowa * 128 + col] =
                    make_float2(c[nl][0] + bv[nl].x, c[nl][1] + bv[nl].y);
            if (rowb < NN)
                *(float2*)&out[(size_t)rowb * 128 + col] =
                    make_float2(c[nl][2] + bv[nl].x, c[nl][3] + bv[nl].y);
        }
    }
}

// ---------------------------------------------------------------------------
// Semantic GEMM, tf32 (R10 WIN, unchanged):
// colsum[c] += sum_n tanh( relu(A[n,:]) @ kw[:,c] + kb[c] )
// ---------------------------------------------------------------------------
#define SEM_TILES ((NN + 63) / 64)
__global__ void __launch_bounds__(256)
semantic_tf32_kernel(const float* __restrict__ A,
                     const float* __restrict__ kw,
                     const float* __restrict__ kb,
                     float* __restrict__ colsum) {
    extern __shared__ float smem[];
    float* sWf = smem;            // 16384 floats
    float* sA  = smem + 16384;    // [64][132]
    __shared__ float scol[128];
    const int tid  = threadIdx.x;
    const int lane = tid & 31;
    const int warp = tid >> 5;
    const int g4   = lane >> 2;
    const int tig  = lane & 3;
    const int rt   = warp & 3;
    const int ch   = warp >> 2;

    for (int i4 = tid; i4 < 4096; i4 += 256) {
        int k  = i4 >> 5;
        int n0 = (i4 & 31) * 4;
        float4 w4 = ((const float4*)kw)[i4];
        float wv[4] = {w4.x, w4.y, w4.z, w4.w};
        int ks = k >> 3;
        int slot = (k & 7) >> 2;
        int km = k & 3;
#pragma unroll
        for (int j = 0; j < 4; ++j) {
            int n = n0 + j;
            int nt = n >> 3;
            int ln = (n & 7) * 4 + km;
            sWf[(((ks * 16) + nt) * 32 + ln) * 2 + slot] = f2tf32f(wv[j]);
        }
    }
    if (tid < 128) scol[tid] = 0.0f;

    float2 kbv[8];
#pragma unroll
    for (int nl = 0; nl < 8; ++nl)
        kbv[nl] = *(const float2*)&kb[(ch * 8 + nl) * 8 + tig * 2];

    float tloc[8][2];
#pragma unroll
    for (int nl = 0; nl < 8; ++nl) { tloc[nl][0] = 0.f; tloc[nl][1] = 0.f; }

    for (int tile = blockIdx.x; tile < SEM_TILES; tile += gridDim.x) {
        __syncthreads();
        const int rowbase = tile * 64;
        const float4* Ab = (const float4*)(A + (size_t)rowbase * 128);
        for (int i4 = tid; i4 < 2048; i4 += 256) {
            int r = i4 >> 5, k4 = i4 & 31;
            float4 v = make_float4(0.f, 0.f, 0.f, 0.f);
            if (rowbase + r < NN) {
                float4 u = Ab[i4];
                v.x = f2tf32f(fmaxf(u.x, 0.f));
                v.y = f2tf32f(fmaxf(u.y, 0.f));
                v.z = f2tf32f(fmaxf(u.z, 0.f));
                v.w = f2tf32f(fmaxf(u.w, 0.f));
            }
            float* dst = &sA[r * 132 + k4 * 4];
            dst[0] = v.x; dst[1] = v.y; dst[2] = v.z; dst[3] = v.w;
        }
        __syncthreads();

        float c[8][4];
#pragma unroll
        for (int nl = 0; nl < 8; ++nl)
#pragma unroll
            for (int j = 0; j < 4; ++j) c[nl][j] = 0.0f;

        const int abase = (rt * 16 + g4) * 132;
#pragma unroll 4
        for (int ks = 0; ks < 16; ++ks) {
            const int k0 = ks * 8;
            uint32_t a0 = __float_as_uint(sA[abase + k0 + tig]);
            uint32_t a1 = __float_as_uint(sA[abase + 8 * 132 + k0 + tig]);
            uint32_t a2 = __float_as_uint(sA[abase + k0 + 4 + tig]);
            uint32_t a3 = __float_as_uint(sA[abase + 8 * 132 + k0 + 4 + tig]);
#pragma unroll
            for (int nl = 0; nl < 8; ++nl) {
                int nt = ch * 8 + nl;
                float2 bf = *(const float2*)&sWf[((ks * 16 + nt) * 32 + lane) * 2];
                mma_tf32(c[nl][0], c[nl][1], c[nl][2], c[nl][3],
                         a0, a1, a2, a3,
                         __float_as_uint(bf.x), __float_as_uint(bf.y));
            }
        }

        const int rowa = rowbase + rt * 16 + g4;
        const int rowb = rowa + 8;
        const bool va = rowa < NN, vb = rowb < NN;
#pragma unroll
        for (int nl = 0; nl < 8; ++nl) {
            if (va) {
                tloc[nl][0] += tanh_fast(c[nl][0] + kbv[nl].x);
                tloc[nl][1] += tanh_fast(c[nl][1] + kbv[nl].y);
            }
            if (vb) {
                tloc[nl][0] += tanh_fast(c[nl][2] + kbv[nl].x);
                tloc[nl][1] += tanh_fast(c[nl][3] + kbv[nl].y);
            }
        }
    }

#pragma unroll
    for (int nl = 0; nl < 8; ++nl) {
        int col = (ch * 8 + nl) * 8 + tig * 2;
        atomicAdd(&scol[col], tloc[nl][0]);
        atomicAdd(&scol[col + 1], tloc[nl][1]);
    }
    __syncthreads();
    if (tid < 128) atomicAdd(&colsum[tid], scol[tid]);
}

// ---------------------------------------------------------------------------
// Per-node attention logits, warp per node
// ---------------------------------------------------------------------------
__global__ void node_attn_kernel(const float* __restrict__ h,
                                 const float* __restrict__ att_src,
                                 const float* __restrict__ att_dst,
                                 float* __restrict__ asrc,
                                 float* __restrict__ adst, int n) {
    int gid = blockIdx.x * blockDim.x + threadIdx.x;
    int node = gid >> 5;
    int lane = gid & 31;
    if (node >= n) return;
    const float* hrow = h + (size_t)node * CC;
    float h00 = hrow[lane];
    float h01 = hrow[lane + 32];
    float h10 = hrow[lane + 64];
    float h11 = hrow[lane + 96];

    float r[8];
#pragma unroll
    for (int t = 0; t < MT; ++t) {
        const float* as = att_src + t * CC;
        const float* ad = att_dst + t * CC;
        r[t * 4 + 0] = h00 * as[lane] + h01 * as[lane + 32];
        r[t * 4 + 1] = h10 * as[lane + 64] + h11 * as[lane + 96];
        r[t * 4 + 2] = h00 * ad[lane] + h01 * ad[lane + 32];
        r[t * 4 + 3] = h10 * ad[lane + 64] + h11 * ad[lane + 96];
    }
#pragma unroll
    for (int i = 0; i < 8; ++i) {
#pragma unroll
        for (int off = 16; off > 0; off >>= 1)
            r[i] += __shfl_xor_sync(0xffffffffu, r[i], off);
    }
    if (lane == 0) {
#pragma unroll
        for (int t = 0; t < MT; ++t) {
            asrc[t * (NN * HH) + node * HH + 0] = r[t * 4 + 0];
            asrc[t * (NN * HH) + node * HH + 1] = r[t * 4 + 1];
            adst[t * (NN * HH) + node * HH + 0] = r[t * 4 + 2];
            adst[t * (NN * HH) + node * HH + 1] = r[t * 4 + 3];
        }
    }
}

// ---------------------------------------------------------------------------
// Edge softmax (measured path): alpha = exp(leaky(...)); asum[dst] += alpha
// ---------------------------------------------------------------------------
__global__ void edge_softmax_kernel(const int* __restrict__ ei,
                                    const float* __restrict__ asrc,
                                    const float* __restrict__ adst,
                                    float* __restrict__ alpha,
                                    float* __restrict__ asum) {
    int e = blockIdx.x * blockDim.x + threadIdx.x;
    if (e >= EE) return;
    int src = ei[e];
    int dst = ei[EE + e];
    float2 s = *(const float2*)&asrc[src * HH];
    float2 d = *(const float2*)&adst[dst * HH];
    float a0 = s.x + d.x;
    float a1 = s.y + d.y;
    float l0 = (a0 > 0.0f) ? a0 : 0.2f * a0;
    float l1 = (a1 > 0.0f) ? a1 : 0.2f * a1;
    float ex0 = expf(l0);
    float ex1 = expf(l1);
    *(float2*)&alpha[(size_t)e * HH] = make_float2(ex0, ex1);
    red_add_v2(&asum[dst * HH], ex0, ex1);
}

// ---------------------------------------------------------------------------
// Edge message, 4 edges per warp (R11 WIN, unchanged)
// ---------------------------------------------------------------------------
__global__ void edge_message_kernel(const int* __restrict__ ei,
                                    const float* __restrict__ expalpha,
                                    const float* __restrict__ asum,
                                    const float* __restrict__ h,
                                    float* __restrict__ outT) {
    int gid = blockIdx.x * blockDim.x + threadIdx.x;
    int w = gid >> 5;
    int lane = gid & 31;
    if (w >= EE / 4) return;
    const int e0 = w * 4;
    const int head = lane >> 4;

    int4 s4 = ((const int4*)ei)[w];
    int4 d4 = ((const int4*)ei)[EE / 4 + w];
    int srcs[4] = {s4.x, s4.y, s4.z, s4.w};
    int dsts[4] = {d4.x, d4.y, d4.z, d4.w};

    float av[4], sv[4];
#pragma unroll
    for (int i = 0; i < 4; ++i)
        av[i] = expalpha[(size_t)(e0 + i) * HH + head];
#pragma unroll
    for (int i = 0; i < 4; ++i)
        sv[i] = asum[dsts[i] * HH + head];

    float4 v[4];
#pragma unroll
    for (int i = 0; i < 4; ++i)
        v[i] = ((const float4*)(h + (size_t)srcs[i] * CC))[lane];

#pragma unroll
    for (int i = 0; i < 4; ++i) {
        float coef = av[i] / (sv[i] + 1e-16f);
        float* o = outT + (size_t)dsts[i] * CC + lane * 4;
        red_add_v4(o, v[i].x * coef, v[i].y * coef, v[i].z * coef, v[i].w * coef);
    }
}

// ---------------------------------------------------------------------------
// Semantic score + softmax (single block, 128 threads)
// ---------------------------------------------------------------------------
__global__ void score_softmax_kernel(const float* __restrict__ q,
                                     const float* __restrict__ colsum,
                                     float* __restrict__ attn) {
    __shared__ float red[128];
    int c = threadIdx.x;
    float s[MT];
#pragma unroll
    for (int m = 0; m < MT; ++m) {
        red[c] = q[c] * colsum[m * CC + c];
        __syncthreads();
        for (int off = 64; off > 0; off >>= 1) {
            if (c < off) red[c] += red[c + off];
            __syncthreads();
        }
        s[m] = red[0] * (1.0f / (float)NN);
        __syncthreads();
    }
    if (c == 0) {
        float mx = fmaxf(s[0], s[1]);
        float e0 = expf(s[0] - mx), e1 = expf(s[1] - mx);
        float inv = 1.0f / (e0 + e1);
        attn[0] = e0 * inv;
        attn[1] = e1 * inv;
    }
}

// ---------------------------------------------------------------------------
// Final linear fused with combine: warp per node
// ---------------------------------------------------------------------------
__global__ void final_linear_kernel(const float* __restrict__ o0,
                                    const float* __restrict__ o1,
                                    const float* __restrict__ attn,
                                    const float* __restrict__ lw,
                                    const float* __restrict__ lb,
                                    float* __restrict__ out) {
    int gid = blockIdx.x * blockDim.x + threadIdx.x;
    int node = gid >> 5;
    int lane = gid & 31;
    if (node >= NN) return;
    float a0 = attn[0], a1 = attn[1];
    float4 u = ((const float4*)(o0 + (size_t)node * CC))[lane];
    float4 v = ((const float4*)(o1 + (size_t)node * CC))[lane];
    float c0 = a0 * fmaxf(u.x, 0.f) + a1 * fmaxf(v.x, 0.f);
    float c1 = a0 * fmaxf(u.y, 0.f) + a1 * fmaxf(v.y, 0.f);
    float c2 = a0 * fmaxf(u.z, 0.f) + a1 * fmaxf(v.z, 0.f);
    float c3 = a0 * fmaxf(u.w, 0.f) + a1 * fmaxf(v.w, 0.f);
    const float* w = lw + lane * 4 * OUTD;
#pragma unroll
    for (int o = 0; o < OUTD; ++o) {
        float p = c0 * w[o] + c1 * w[OUTD + o] + c2 * w[2 * OUTD + o]
                + c3 * w[3 * OUTD + o];
#pragma unroll
        for (int off = 16; off > 0; off >>= 1)
            p += __shfl_xor_sync(0xffffffffu, p, off);
        if (lane == 0) out[(size_t)node * OUTD + o] = p + lb[o];
    }
}

// ---------------------------------------------------------------------------
// Host side
// ---------------------------------------------------------------------------
struct Scratch {
    float* h; float* out0; float* out1;
    float* asrc; float* adst; float* alpha;
    float* asum; float* colsum; float* attn;
};

#define GEMM_BLOCKS 296
#define SEM_SMEM  ((16384 + 64 * 132) * sizeof(float))
#define PROJ64_SMEM  ((64 * 128 + 64 * 68) * sizeof(float))
#define PROJ128_SMEM ((128 * 128 + 64 * 132) * sizeof(float))

static void run_han_layer(const float* input, const float* input2, int Kin,
                          const float* pw, const float* pb,
                          const float* att_src, const float* att_dst,
                          const float* q, const float* kw, const float* kb,
                          const int* ei0, const int* ei1, const Scratch& S) {
    if (Kin == 64) {
        proj_tf32_kernel<64, false><<<GEMM_BLOCKS, 256, PROJ64_SMEM>>>(
            input, nullptr, nullptr, pw, pb, S.h);
    } else {
        proj_tf32_kernel<128, true><<<GEMM_BLOCKS, 256, PROJ128_SMEM>>>(
            input, input2, S.attn, pw, pb, S.h);
    }

    node_attn_kernel<<<(NN * 32 + 255) / 256, 256>>>(S.h, att_src, att_dst,
                                                     S.asrc, S.adst, NN);

    cudaMemsetAsync(S.colsum, 0, MT * CC * sizeof(float));

    const int* eis[2] = {ei0, ei1};
    float* outs[2] = {S.out0, S.out1};
    for (int t = 0; t < MT; ++t) {
        cudaMemsetAsync(S.asum, 0, NN * HH * sizeof(float));
        cudaMemsetAsync(outs[t], 0, (size_t)NN * CC * sizeof(float));

        const float* asrc_t = S.asrc + t * (NN * HH);
        const float* adst_t = S.adst + t * (NN * HH);

        edge_softmax_kernel<<<(EE + 255) / 256, 256>>>(eis[t], asrc_t, adst_t,
                                                       S.alpha, S.asum);
        edge_message_kernel<<<(EE * 8 + 255) / 256, 256>>>(eis[t], S.alpha,
                                                           S.asum, S.h, outs[t]);
        semantic_tf32_kernel<<<GEMM_BLOCKS, 256, SEM_SMEM>>>(
            outs[t], kw, kb, S.colsum + t * CC);
    }

    score_softmax_kernel<<<1, 128>>>(q, S.colsum, S.attn);
}

extern "C" void kernel_launch(void* const* d_in, const int* in_sizes, int n_in,
                              void* d_out, int out_size) {
    const float *x = nullptr, *p1w = nullptr;
    const float *b128[6] = {nullptr};
    const float *a256[4] = {nullptr};
    const float *w16384[3] = {nullptr};
    const float *lin_w = nullptr, *lin_b = nullptr;
    const int *ei[2] = {nullptr, nullptr};
    int n128 = 0, n256 = 0, n16384 = 0, nei = 0;

    for (int i = 0; i < n_in; ++i) {
        int sz = in_sizes[i];
        const void* p = d_in[i];
        switch (sz) {
            case NN * FIN:      x = (const float*)p; break;
            case 2 * EE:        if (nei < 2) ei[nei++] = (const int*)p; break;
            case FIN * CC:      p1w = (const float*)p; break;
            case CC * CC:       if (n16384 < 3) w16384[n16384++] = (const float*)p; break;
            case MT * HH * DD:  if (n256 < 4) a256[n256++] = (const float*)p; break;
            case CC:            if (n128 < 6) b128[n128++] = (const float*)p; break;
            case CC * OUTD:     lin_w = (const float*)p; break;
            case OUTD:          lin_b = (const float*)p; break;
            default: break;
        }
    }
    const float* p1_kw = w16384[0];
    const float* p2w   = w16384[1];
    const float* p2_kw = w16384[2];
    const float *p1_pb = b128[0], *p1_q = b128[1], *p1_kb = b128[2];
    const float *p2_pb = b128[3], *p2_q = b128[4], *p2_kb = b128[5];
    const float *p1_as = a256[0], *p1_ad = a256[1];
    const float *p2_as = a256[2], *p2_ad = a256[3];

    (void)cudaFuncSetAttribute(proj_tf32_kernel<64, false>,
                               cudaFuncAttributeMaxDynamicSharedMemorySize, 110 * 1024);
    (void)cudaFuncSetAttribute(proj_tf32_kernel<128, true>,
                               cudaFuncAttributeMaxDynamicSharedMemorySize, 110 * 1024);
    (void)cudaFuncSetAttribute(semantic_tf32_kernel,
                               cudaFuncAttributeMaxDynamicSharedMemorySize, 110 * 1024);

    Scratch S;
    cudaGetSymbolAddress((void**)&S.h, g_h);
    cudaGetSymbolAddress((void**)&S.out0, g_out0);
    cudaGetSymbolAddress((void**)&S.out1, g_out1);
    cudaGetSymbolAddress((void**)&S.asrc, g_asrc);
    cudaGetSymbolAddress((void**)&S.adst, g_adst);
    cudaGetSymbolAddress((void**)&S.alpha, g_alpha);
    cudaGetSymbolAddress((void**)&S.asum, g_asum);
    cudaGetSymbolAddress((void**)&S.colsum, g_colsum);
    cudaGetSymbolAddress((void**)&S.attn, g_attn);

    // Layer 1: IN=64 -> C=128
    run_han_layer(x, nullptr, 64, p1w, p1_pb, p1_as, p1_ad, p1_q, p1_kw, p1_kb,
                  ei[0], ei[1], S);
    // Layer 2: combine fused into tf32 projection A-stage
    run_han_layer(S.out0, S.out1, 128, p2w, p2_pb, p2_as, p2_ad, p2_q, p2_kw,
                  p2_kb, ei[0], ei[1], S);

    // Final classifier (combine fused)
    final_linear_kernel<<<(NN * 32 + 255) / 256, 256>>>(
        S.out0, S.out1, S.attn, lin_w, lin_b, (float*)d_out);
}